// round 4
// baseline (speedup 1.0000x reference)
#include <cuda_runtime.h>
#include <cuda_bf16.h>
#include <cstdint>
#include <cstddef>

// Problem constants
#define DIMC   768
#define NHEADS 12
#define HDIM   64
#define BATCH  8
#define LQ     1024
#define LKV    1024
#define SCALE  0.125f

#define MROWS  (BATCH * LQ)     // 8192

// fp32 scratch (attention I/O)
__device__ float g_Q [(size_t)MROWS * DIMC];
__device__ float g_KV[(size_t)MROWS * 2 * DIMC];
__device__ float g_O [(size_t)MROWS * DIMC];

// bf16 split scratch
__device__ __nv_bfloat16 g_qh [(size_t)MROWS * DIMC];
__device__ __nv_bfloat16 g_ql [(size_t)MROWS * DIMC];
__device__ __nv_bfloat16 g_kvh[(size_t)MROWS * DIMC];
__device__ __nv_bfloat16 g_kvl[(size_t)MROWS * DIMC];
__device__ __nv_bfloat16 g_oh [(size_t)MROWS * DIMC];
__device__ __nv_bfloat16 g_ol [(size_t)MROWS * DIMC];
__device__ __nv_bfloat16 g_wqh[(size_t)DIMC * DIMC];
__device__ __nv_bfloat16 g_wql[(size_t)DIMC * DIMC];
__device__ __nv_bfloat16 g_wkh[(size_t)2 * DIMC * DIMC];
__device__ __nv_bfloat16 g_wkl[(size_t)2 * DIMC * DIMC];
__device__ __nv_bfloat16 g_wph[(size_t)DIMC * DIMC];
__device__ __nv_bfloat16 g_wpl[(size_t)DIMC * DIMC];

// ---------------------------------------------------------------------------
__device__ __forceinline__ uint32_t smem_u32(const void* p) {
    uint32_t a;
    asm("{ .reg .u64 t; cvta.to.shared.u64 t, %1; cvt.u32.u64 %0, t; }" : "=r"(a) : "l"(p));
    return a;
}
__device__ __forceinline__ void ldsm4(uint32_t* r, uint32_t addr) {
    asm volatile("ldmatrix.sync.aligned.m8n8.x4.shared.b16 {%0,%1,%2,%3}, [%4];"
        : "=r"(r[0]), "=r"(r[1]), "=r"(r[2]), "=r"(r[3]) : "r"(addr));
}
__device__ __forceinline__ void mma16816(float* d, const uint32_t* a, const uint32_t* b) {
    asm volatile("mma.sync.aligned.m16n8k16.row.col.f32.bf16.bf16.f32 "
        "{%0,%1,%2,%3}, {%4,%5,%6,%7}, {%8,%9}, {%0,%1,%2,%3};"
        : "+f"(d[0]), "+f"(d[1]), "+f"(d[2]), "+f"(d[3])
        : "r"(a[0]), "r"(a[1]), "r"(a[2]), "r"(a[3]), "r"(b[0]), "r"(b[1]));
}
__device__ __forceinline__ void cp16(uint32_t dst, const void* src) {
    asm volatile("cp.async.cg.shared.global [%0], [%1], 16;" :: "r"(dst), "l"(src) : "memory");
}
#define CP_COMMIT() asm volatile("cp.async.commit_group;" ::: "memory")

// MUFU-free exp2-based exp(x) for x <= 0 (softmax weights).
// t = x*log2e; n = round(t) via magic constant; 2^f Taylor deg-5 on [-0.5,0.5].
__device__ __forceinline__ float exp_fast(float x) {
    float t = fmaf(x, 1.4426950408889634f, 0.f);
    t = fmaxf(t, -80.f);
    float y = t + 12582912.f;                       // round-to-nearest int (RN mode)
    int   n = __float_as_int(y) - 0x4B400000;       // signed integer part
    float f = t - (y - 12582912.f);                 // f in [-0.5, 0.5]
    float p = 1.3333558146e-3f;
    p = fmaf(p, f, 9.6181291076e-3f);
    p = fmaf(p, f, 5.5504108664e-2f);
    p = fmaf(p, f, 2.4022650695e-1f);
    p = fmaf(p, f, 6.9314718056e-1f);
    p = fmaf(p, f, 1.0f);
    return p * __int_as_float((n + 127) << 23);
}

// swizzled byte offset inside a 128B-row tile: row, c16 = 16B-column (0..7)
__device__ __forceinline__ uint32_t swz(int row, int c16) {
    return (uint32_t)(row * 128 + ((c16 ^ (row & 7)) << 4));
}

// stage one 128x64-bf16 buffer (16KB) via cp.async (per-thread 4x16B)
__device__ __forceinline__ void stage_buf(uint32_t sdst, const __nv_bfloat16* rowbase,
                                          int K, int k0, int crow, int chalf) {
    const __nv_bfloat16* src = rowbase + (size_t)crow * K + k0 + chalf * 8;
    uint32_t dbase = sdst + (uint32_t)crow * 128;
    int rx = crow & 7;
#pragma unroll
    for (int j = 0; j < 4; j++) {
        int c16 = chalf + j;
        cp16(dbase + (((c16 ^ rx)) << 4), src + j * 8);
    }
}

// ---------------------------------------------------------------------------
// C[M,N] = A[M,K] @ W[N,K]^T (+bias), bf16-split 3-pass via mma.sync.
// ---------------------------------------------------------------------------
#define STG_STRIDE 65536
#define BUF_AH 0
#define BUF_AL 16384
#define BUF_WH 32768
#define BUF_WL 49152

__global__ __launch_bounds__(256, 1)
void gemm_mma(const __nv_bfloat16* __restrict__ Ah, const __nv_bfloat16* __restrict__ Al,
              const __nv_bfloat16* __restrict__ Wh, const __nv_bfloat16* __restrict__ Wl,
              const float* __restrict__ bias, float* __restrict__ C, int N, int K)
{
    extern __shared__ char sm[];
    const uint32_t smb = smem_u32(sm);
    const int tid = threadIdx.x;
    const int wid = tid >> 5, lane = tid & 31;
    const int wm = wid >> 2, wn = wid & 3;
    const int m0 = blockIdx.y * 128, n0 = blockIdx.x * 128;

    const int crow = tid >> 1;
    const int chalf = (tid & 1) * 4;

    const __nv_bfloat16* Ahb = Ah + (size_t)m0 * K;
    const __nv_bfloat16* Alb = Al + (size_t)m0 * K;
    const __nv_bfloat16* Whb = Wh + (size_t)n0 * K;
    const __nv_bfloat16* Wlb = Wl + (size_t)n0 * K;

    const int g = lane >> 3, r = lane & 7;
    const int arl = (g & 1) * 8 + r;
    const int acs = g >> 1;
    const int brl = (g >> 1) * 8 + r;
    const int bcs = g & 1;

    float acc[4][4][4];
#pragma unroll
    for (int i = 0; i < 4; i++)
#pragma unroll
        for (int j = 0; j < 4; j++)
#pragma unroll
            for (int k = 0; k < 4; k++) acc[i][j][k] = 0.f;

    const int NC = K >> 6;

    {
        uint32_t sb = smb;
        stage_buf(sb + BUF_AH, Ahb, K, 0, crow, chalf);
        stage_buf(sb + BUF_AL, Alb, K, 0, crow, chalf);
        stage_buf(sb + BUF_WH, Whb, K, 0, crow, chalf);
        stage_buf(sb + BUF_WL, Wlb, K, 0, crow, chalf);
        CP_COMMIT();
    }

    for (int c = 0; c < NC; ++c) {
        if (c + 1 < NC) {
            uint32_t sb = smb + ((c + 1) & 1) * STG_STRIDE;
            int k0 = (c + 1) << 6;
            stage_buf(sb + BUF_AH, Ahb, K, k0, crow, chalf);
            stage_buf(sb + BUF_AL, Alb, K, k0, crow, chalf);
            stage_buf(sb + BUF_WH, Whb, K, k0, crow, chalf);
            stage_buf(sb + BUF_WL, Wlb, K, k0, crow, chalf);
            CP_COMMIT();
            asm volatile("cp.async.wait_group 1;" ::: "memory");
        } else {
            asm volatile("cp.async.wait_group 0;" ::: "memory");
        }
        __syncthreads();

        const uint32_t sb = smb + (c & 1) * STG_STRIDE;
        const uint32_t bAh = sb + BUF_AH, bAl = sb + BUF_AL;
        const uint32_t bWh = sb + BUF_WH, bWl = sb + BUF_WL;

#pragma unroll
        for (int s = 0; s < 4; ++s) {
            uint32_t afr[4][4], bh[2][4], bl[2][4];
#pragma unroll
            for (int mt = 0; mt < 4; ++mt)
                ldsm4(afr[mt], bAh + swz(wm * 64 + mt * 16 + arl, s * 2 + acs));
#pragma unroll
            for (int p = 0; p < 2; ++p)
                ldsm4(bh[p], bWh + swz(wn * 32 + p * 16 + brl, s * 2 + bcs));
#pragma unroll
            for (int p = 0; p < 2; ++p)
                ldsm4(bl[p], bWl + swz(wn * 32 + p * 16 + brl, s * 2 + bcs));

#pragma unroll
            for (int mt = 0; mt < 4; ++mt)
#pragma unroll
                for (int nt = 0; nt < 4; ++nt)
                    mma16816(acc[mt][nt], afr[mt], &bh[nt >> 1][(nt & 1) * 2]);
#pragma unroll
            for (int mt = 0; mt < 4; ++mt)
#pragma unroll
                for (int nt = 0; nt < 4; ++nt)
                    mma16816(acc[mt][nt], afr[mt], &bl[nt >> 1][(nt & 1) * 2]);
#pragma unroll
            for (int mt = 0; mt < 4; ++mt)
                ldsm4(afr[mt], bAl + swz(wm * 64 + mt * 16 + arl, s * 2 + acs));
#pragma unroll
            for (int mt = 0; mt < 4; ++mt)
#pragma unroll
                for (int nt = 0; nt < 4; ++nt)
                    mma16816(acc[mt][nt], afr[mt], &bh[nt >> 1][(nt & 1) * 2]);
        }
        __syncthreads();
    }

    const int er = lane >> 2, ec = (lane & 3) * 2;
#pragma unroll
    for (int mt = 0; mt < 4; ++mt) {
#pragma unroll
        for (int nt = 0; nt < 4; ++nt) {
            int grow = m0 + wm * 64 + mt * 16 + er;
            int gcol = n0 + wn * 32 + nt * 8 + ec;
            float b0 = 0.f, b1 = 0.f;
            if (bias) { b0 = bias[gcol]; b1 = bias[gcol + 1]; }
            float2 v0 = make_float2(acc[mt][nt][0] + b0, acc[mt][nt][1] + b1);
            float2 v1 = make_float2(acc[mt][nt][2] + b0, acc[mt][nt][3] + b1);
            *(float2*)(C + (size_t)grow * N + gcol) = v0;
            *(float2*)(C + (size_t)(grow + 8) * N + gcol) = v1;
        }
    }
}

// ---------------------------------------------------------------------------
// fp32 -> (hi, lo) bf16 split, vectorized x4
// ---------------------------------------------------------------------------
__global__ __launch_bounds__(256)
void cvt_split(const float4* __restrict__ in, uint2* __restrict__ hi,
               uint2* __restrict__ lo, int n4)
{
    int i = blockIdx.x * blockDim.x + threadIdx.x;
    if (i >= n4) return;
    float4 x = in[i];
    __nv_bfloat162 h01 = __floats2bfloat162_rn(x.x, x.y);
    __nv_bfloat162 h23 = __floats2bfloat162_rn(x.z, x.w);
    float r0 = x.x - __low2float(h01), r1 = x.y - __high2float(h01);
    float r2 = x.z - __low2float(h23), r3 = x.w - __high2float(h23);
    __nv_bfloat162 l01 = __floats2bfloat162_rn(r0, r1);
    __nv_bfloat162 l23 = __floats2bfloat162_rn(r2, r3);
    hi[i] = make_uint2(*(uint32_t*)&h01, *(uint32_t*)&h23);
    lo[i] = make_uint2(*(uint32_t*)&l01, *(uint32_t*)&l23);
}

// ---------------------------------------------------------------------------
// Fused flash-style attention — MUFU-free exp.
// ---------------------------------------------------------------------------
__global__ __launch_bounds__(128)
void attn_kernel(const float* __restrict__ Qb, const float* __restrict__ KVb,
                 const float* __restrict__ pos, float* __restrict__ Ob)
{
    extern __shared__ float smf[];
    float* Ks = smf;
    float* Vs = smf + 64 * 64;
    float* Ps = smf + 2 * 64 * 64;

    const int tid = threadIdx.x;
    const int b = blockIdx.z, h = blockIdx.y;
    const int q0 = blockIdx.x * 128;

    const float* Qbase = Qb + ((size_t)(b * LQ + q0)) * DIMC + h * HDIM;
    for (int i = tid; i < 128 * 64; i += 128) {
        int rr = i >> 6, cc = i & 63;
        Ps[rr * 65 + cc] = Qbase[(size_t)rr * DIMC + cc];
    }
    __syncthreads();
    float Qr[64];
#pragma unroll
    for (int d = 0; d < 64; d++) Qr[d] = Ps[tid * 65 + d];

    float O[64];
#pragma unroll
    for (int d = 0; d < 64; d++) O[d] = 0.f;
    float mv = -1e30f, l = 0.f;

    const float* Kbase   = KVb + (size_t)b * LKV * (2 * DIMC) + h * HDIM;
    const float* Vbase   = Kbase + DIMC;
    const float* posbase = pos + ((size_t)(h * LQ + q0)) * LKV;
    float* myP = Ps + tid * 65;

    for (int kv0 = 0; kv0 < LKV; kv0 += 64) {
        __syncthreads();
        for (int i = tid; i < 64 * 64; i += 128) {
            int rr = i >> 6, cc = i & 63;
            Ks[rr * 64 + cc] = Kbase[(size_t)(kv0 + rr) * (2 * DIMC) + cc];
            Vs[rr * 64 + cc] = Vbase[(size_t)(kv0 + rr) * (2 * DIMC) + cc];
        }
        for (int i = tid; i < 128 * 64; i += 128) {
            int rr = i >> 6, cc = i & 63;
            Ps[rr * 65 + cc] = posbase[(size_t)rr * LKV + kv0 + cc];
        }
        __syncthreads();

        float tmax = mv;
#pragma unroll 2
        for (int kv = 0; kv < 64; kv++) {
            const float4* kr = (const float4*)(Ks + kv * 64);
            float s0 = 0.f, s1 = 0.f, s2 = 0.f, s3 = 0.f;
#pragma unroll
            for (int d4 = 0; d4 < 16; d4++) {
                float4 kk = kr[d4];
                s0 += Qr[4 * d4 + 0] * kk.x;
                s1 += Qr[4 * d4 + 1] * kk.y;
                s2 += Qr[4 * d4 + 2] * kk.z;
                s3 += Qr[4 * d4 + 3] * kk.w;
            }
            float s = (s0 + s1) + (s2 + s3);
            s = s * SCALE + myP[kv];
            myP[kv] = s;
            tmax = fmaxf(tmax, s);
        }

        float alpha = exp_fast(mv - tmax);
        mv = tmax;
        l *= alpha;
#pragma unroll
        for (int d = 0; d < 64; d++) O[d] *= alpha;

        for (int kv = 0; kv < 64; kv++) {
            float p = exp_fast(myP[kv] - mv);
            l += p;
            const float4* vr = (const float4*)(Vs + kv * 64);
#pragma unroll
            for (int d4 = 0; d4 < 16; d4++) {
                float4 vv = vr[d4];
                O[4 * d4 + 0] += p * vv.x;
                O[4 * d4 + 1] += p * vv.y;
                O[4 * d4 + 2] += p * vv.z;
                O[4 * d4 + 3] += p * vv.w;
            }
        }
    }

    const float inv = 1.f / l;
    float* orow = Ob + ((size_t)(b * LQ + q0 + tid)) * DIMC + h * HDIM;
#pragma unroll
    for (int d = 0; d < 64; d++) orow[d] = O[d] * inv;
}

// ---------------------------------------------------------------------------
extern "C" void kernel_launch(void* const* d_in, const int* in_sizes, int n_in,
                              void* d_out, int out_size)
{
    (void)in_sizes; (void)n_in; (void)out_size;
    const float* q     = (const float*)d_in[0];
    const float* kv    = (const float*)d_in[1];
    const float* pos   = (const float*)d_in[2];
    const float* Wq    = (const float*)d_in[3];
    const float* Wkv   = (const float*)d_in[4];
    const float* Wproj = (const float*)d_in[5];
    const float* bproj = (const float*)d_in[6];
    float* out = (float*)d_out;

    float *gQ, *gKV, *gO;
    cudaGetSymbolAddress((void**)&gQ,  g_Q);
    cudaGetSymbolAddress((void**)&gKV, g_KV);
    cudaGetSymbolAddress((void**)&gO,  g_O);
    __nv_bfloat16 *qh, *ql, *kvh, *kvl, *oh, *ol, *wqh, *wql, *wkh, *wkl, *wph, *wpl;
    cudaGetSymbolAddress((void**)&qh,  g_qh);   cudaGetSymbolAddress((void**)&ql,  g_ql);
    cudaGetSymbolAddress((void**)&kvh, g_kvh);  cudaGetSymbolAddress((void**)&kvl, g_kvl);
    cudaGetSymbolAddress((void**)&oh,  g_oh);   cudaGetSymbolAddress((void**)&ol,  g_ol);
    cudaGetSymbolAddress((void**)&wqh, g_wqh);  cudaGetSymbolAddress((void**)&wql, g_wql);
    cudaGetSymbolAddress((void**)&wkh, g_wkh);  cudaGetSymbolAddress((void**)&wkl, g_wkl);
    cudaGetSymbolAddress((void**)&wph, g_wph);  cudaGetSymbolAddress((void**)&wpl, g_wpl);

    static bool attr_done = false;
    if (!attr_done) {
        cudaFuncSetAttribute(gemm_mma, cudaFuncAttributeMaxDynamicSharedMemorySize, 2 * STG_STRIDE);
        cudaFuncSetAttribute(attn_kernel, cudaFuncAttributeMaxDynamicSharedMemorySize,
                             (2 * 64 * 64 + 128 * 65) * (int)sizeof(float));
        attr_done = true;
    }
    const int ATTN_SMEM = (2 * 64 * 64 + 128 * 65) * sizeof(float);
    const int GEMM_SMEM = 2 * STG_STRIDE;

    const int M = MROWS;

    auto cvt = [](const float* p, __nv_bfloat16* h, __nv_bfloat16* l, size_t n) {
        int n4 = (int)(n / 4);
        cvt_split<<<(n4 + 255) / 256, 256>>>((const float4*)p, (uint2*)h, (uint2*)l, n4);
    };

    cvt(q,     qh,  ql,  (size_t)M * DIMC);
    cvt(kv,    kvh, kvl, (size_t)M * DIMC);
    cvt(Wq,    wqh, wql, (size_t)DIMC * DIMC);
    cvt(Wkv,   wkh, wkl, (size_t)2 * DIMC * DIMC);
    cvt(Wproj, wph, wpl, (size_t)DIMC * DIMC);

    gemm_mma<<<dim3(DIMC / 128, M / 128), 256, GEMM_SMEM>>>(qh, ql, wqh, wql, nullptr, gQ, DIMC, DIMC);
    gemm_mma<<<dim3(2 * DIMC / 128, M / 128), 256, GEMM_SMEM>>>(kvh, kvl, wkh, wkl, nullptr, gKV, 2 * DIMC, DIMC);
    attn_kernel<<<dim3(LQ / 128, NHEADS, BATCH), 128, ATTN_SMEM>>>(gQ, gKV, pos, gO);
    cvt(gO, oh, ol, (size_t)M * DIMC);
    gemm_mma<<<dim3(DIMC / 128, M / 128), 256, GEMM_SMEM>>>(oh, ol, wph, wpl, bproj, out, DIMC, DIMC);
}

// round 5
// speedup vs baseline: 1.1153x; 1.1153x over previous
#include <cuda_runtime.h>
#include <cuda_bf16.h>
#include <cstdint>
#include <cstddef>

// Problem constants
#define DIMC   768
#define NHEADS 12
#define HDIM   64
#define BATCH  8
#define LQ     1024
#define LKV    1024
#define SCALE  0.125f
#define KVSTR  (2 * DIMC)       // 1536

#define MROWS  (BATCH * LQ)     // 8192

// fp32 scratch (attention I/O)
__device__ float g_Q [(size_t)MROWS * DIMC];
__device__ float g_KV[(size_t)MROWS * 2 * DIMC];
__device__ float g_O [(size_t)MROWS * DIMC];

// bf16 split scratch
__device__ __nv_bfloat16 g_qh [(size_t)MROWS * DIMC];
__device__ __nv_bfloat16 g_ql [(size_t)MROWS * DIMC];
__device__ __nv_bfloat16 g_kvh[(size_t)MROWS * DIMC];
__device__ __nv_bfloat16 g_kvl[(size_t)MROWS * DIMC];
__device__ __nv_bfloat16 g_oh [(size_t)MROWS * DIMC];
__device__ __nv_bfloat16 g_ol [(size_t)MROWS * DIMC];
__device__ __nv_bfloat16 g_wqh[(size_t)DIMC * DIMC];
__device__ __nv_bfloat16 g_wql[(size_t)DIMC * DIMC];
__device__ __nv_bfloat16 g_wkh[(size_t)2 * DIMC * DIMC];
__device__ __nv_bfloat16 g_wkl[(size_t)2 * DIMC * DIMC];
__device__ __nv_bfloat16 g_wph[(size_t)DIMC * DIMC];
__device__ __nv_bfloat16 g_wpl[(size_t)DIMC * DIMC];

// ---------------------------------------------------------------------------
__device__ __forceinline__ uint32_t smem_u32(const void* p) {
    uint32_t a;
    asm("{ .reg .u64 t; cvta.to.shared.u64 t, %1; cvt.u32.u64 %0, t; }" : "=r"(a) : "l"(p));
    return a;
}
__device__ __forceinline__ void ldsm4(uint32_t* r, uint32_t addr) {
    asm volatile("ldmatrix.sync.aligned.m8n8.x4.shared.b16 {%0,%1,%2,%3}, [%4];"
        : "=r"(r[0]), "=r"(r[1]), "=r"(r[2]), "=r"(r[3]) : "r"(addr));
}
__device__ __forceinline__ void mma16816(float* d, const uint32_t* a, const uint32_t* b) {
    asm volatile("mma.sync.aligned.m16n8k16.row.col.f32.bf16.bf16.f32 "
        "{%0,%1,%2,%3}, {%4,%5,%6,%7}, {%8,%9}, {%0,%1,%2,%3};"
        : "+f"(d[0]), "+f"(d[1]), "+f"(d[2]), "+f"(d[3])
        : "r"(a[0]), "r"(a[1]), "r"(a[2]), "r"(a[3]), "r"(b[0]), "r"(b[1]));
}
__device__ __forceinline__ void cp16(uint32_t dst, const void* src) {
    asm volatile("cp.async.cg.shared.global [%0], [%1], 16;" :: "r"(dst), "l"(src) : "memory");
}
#define CP_COMMIT() asm volatile("cp.async.commit_group;" ::: "memory")

// swizzled byte offset inside a 128B-row tile: row, c16 = 16B-column (0..7)
__device__ __forceinline__ uint32_t swz(int row, int c16) {
    return (uint32_t)(row * 128 + ((c16 ^ (row & 7)) << 4));
}

// stage one 128x64-bf16 buffer (16KB) via cp.async (per-thread 4x16B)
__device__ __forceinline__ void stage_buf(uint32_t sdst, const __nv_bfloat16* rowbase,
                                          int K, int k0, int crow, int chalf) {
    const __nv_bfloat16* src = rowbase + (size_t)crow * K + k0 + chalf * 8;
    uint32_t dbase = sdst + (uint32_t)crow * 128;
    int rx = crow & 7;
#pragma unroll
    for (int j = 0; j < 4; j++) {
        int c16 = chalf + j;
        cp16(dbase + (((c16 ^ rx)) << 4), src + j * 8);
    }
}

// ---------------------------------------------------------------------------
// C[M,N] = A[M,K] @ W[N,K]^T (+bias), bf16-split 3-pass via mma.sync.
// ---------------------------------------------------------------------------
#define STG_STRIDE 65536
#define BUF_AH 0
#define BUF_AL 16384
#define BUF_WH 32768
#define BUF_WL 49152

__global__ __launch_bounds__(256, 1)
void gemm_mma(const __nv_bfloat16* __restrict__ Ah, const __nv_bfloat16* __restrict__ Al,
              const __nv_bfloat16* __restrict__ Wh, const __nv_bfloat16* __restrict__ Wl,
              const float* __restrict__ bias, float* __restrict__ C, int N, int K)
{
    extern __shared__ char sm[];
    const uint32_t smb = smem_u32(sm);
    const int tid = threadIdx.x;
    const int wid = tid >> 5, lane = tid & 31;
    const int wm = wid >> 2, wn = wid & 3;
    const int m0 = blockIdx.y * 128, n0 = blockIdx.x * 128;

    const int crow = tid >> 1;
    const int chalf = (tid & 1) * 4;

    const __nv_bfloat16* Ahb = Ah + (size_t)m0 * K;
    const __nv_bfloat16* Alb = Al + (size_t)m0 * K;
    const __nv_bfloat16* Whb = Wh + (size_t)n0 * K;
    const __nv_bfloat16* Wlb = Wl + (size_t)n0 * K;

    const int g = lane >> 3, r = lane & 7;
    const int arl = (g & 1) * 8 + r;
    const int acs = g >> 1;
    const int brl = (g >> 1) * 8 + r;
    const int bcs = g & 1;

    float acc[4][4][4];
#pragma unroll
    for (int i = 0; i < 4; i++)
#pragma unroll
        for (int j = 0; j < 4; j++)
#pragma unroll
            for (int k = 0; k < 4; k++) acc[i][j][k] = 0.f;

    const int NC = K >> 6;

    {
        uint32_t sb = smb;
        stage_buf(sb + BUF_AH, Ahb, K, 0, crow, chalf);
        stage_buf(sb + BUF_AL, Alb, K, 0, crow, chalf);
        stage_buf(sb + BUF_WH, Whb, K, 0, crow, chalf);
        stage_buf(sb + BUF_WL, Wlb, K, 0, crow, chalf);
        CP_COMMIT();
    }

    for (int c = 0; c < NC; ++c) {
        if (c + 1 < NC) {
            uint32_t sb = smb + ((c + 1) & 1) * STG_STRIDE;
            int k0 = (c + 1) << 6;
            stage_buf(sb + BUF_AH, Ahb, K, k0, crow, chalf);
            stage_buf(sb + BUF_AL, Alb, K, k0, crow, chalf);
            stage_buf(sb + BUF_WH, Whb, K, k0, crow, chalf);
            stage_buf(sb + BUF_WL, Wlb, K, k0, crow, chalf);
            CP_COMMIT();
            asm volatile("cp.async.wait_group 1;" ::: "memory");
        } else {
            asm volatile("cp.async.wait_group 0;" ::: "memory");
        }
        __syncthreads();

        const uint32_t sb = smb + (c & 1) * STG_STRIDE;
        const uint32_t bAh = sb + BUF_AH, bAl = sb + BUF_AL;
        const uint32_t bWh = sb + BUF_WH, bWl = sb + BUF_WL;

#pragma unroll
        for (int s = 0; s < 4; ++s) {
            uint32_t afr[4][4], bh[2][4], bl[2][4];
#pragma unroll
            for (int mt = 0; mt < 4; ++mt)
                ldsm4(afr[mt], bAh + swz(wm * 64 + mt * 16 + arl, s * 2 + acs));
#pragma unroll
            for (int p = 0; p < 2; ++p)
                ldsm4(bh[p], bWh + swz(wn * 32 + p * 16 + brl, s * 2 + bcs));
#pragma unroll
            for (int p = 0; p < 2; ++p)
                ldsm4(bl[p], bWl + swz(wn * 32 + p * 16 + brl, s * 2 + bcs));

#pragma unroll
            for (int mt = 0; mt < 4; ++mt)
#pragma unroll
                for (int nt = 0; nt < 4; ++nt)
                    mma16816(acc[mt][nt], afr[mt], &bh[nt >> 1][(nt & 1) * 2]);
#pragma unroll
            for (int mt = 0; mt < 4; ++mt)
#pragma unroll
                for (int nt = 0; nt < 4; ++nt)
                    mma16816(acc[mt][nt], afr[mt], &bl[nt >> 1][(nt & 1) * 2]);
#pragma unroll
            for (int mt = 0; mt < 4; ++mt)
                ldsm4(afr[mt], bAl + swz(wm * 64 + mt * 16 + arl, s * 2 + acs));
#pragma unroll
            for (int mt = 0; mt < 4; ++mt)
#pragma unroll
                for (int nt = 0; nt < 4; ++nt)
                    mma16816(acc[mt][nt], afr[mt], &bh[nt >> 1][(nt & 1) * 2]);
        }
        __syncthreads();
    }

    const int er = lane >> 2, ec = (lane & 3) * 2;
#pragma unroll
    for (int mt = 0; mt < 4; ++mt) {
#pragma unroll
        for (int nt = 0; nt < 4; ++nt) {
            int grow = m0 + wm * 64 + mt * 16 + er;
            int gcol = n0 + wn * 32 + nt * 8 + ec;
            float b0 = 0.f, b1 = 0.f;
            if (bias) { b0 = bias[gcol]; b1 = bias[gcol + 1]; }
            float2 v0 = make_float2(acc[mt][nt][0] + b0, acc[mt][nt][1] + b1);
            float2 v1 = make_float2(acc[mt][nt][2] + b0, acc[mt][nt][3] + b1);
            *(float2*)(C + (size_t)grow * N + gcol) = v0;
            *(float2*)(C + (size_t)(grow + 8) * N + gcol) = v1;
        }
    }
}

// ---------------------------------------------------------------------------
// fp32 -> (hi, lo) bf16 split, vectorized x4
// ---------------------------------------------------------------------------
__global__ __launch_bounds__(256)
void cvt_split(const float4* __restrict__ in, uint2* __restrict__ hi,
               uint2* __restrict__ lo, int n4)
{
    int i = blockIdx.x * blockDim.x + threadIdx.x;
    if (i >= n4) return;
    float4 x = in[i];
    __nv_bfloat162 h01 = __floats2bfloat162_rn(x.x, x.y);
    __nv_bfloat162 h23 = __floats2bfloat162_rn(x.z, x.w);
    float r0 = x.x - __low2float(h01), r1 = x.y - __high2float(h01);
    float r2 = x.z - __low2float(h23), r3 = x.w - __high2float(h23);
    __nv_bfloat162 l01 = __floats2bfloat162_rn(r0, r1);
    __nv_bfloat162 l23 = __floats2bfloat162_rn(r2, r3);
    hi[i] = make_uint2(*(uint32_t*)&h01, *(uint32_t*)&h23);
    lo[i] = make_uint2(*(uint32_t*)&l01, *(uint32_t*)&l23);
}

// ---------------------------------------------------------------------------
// Fused flash-style attention — cp.async double-buffered staging.
// Grid (Lq/128, H, B), 128 threads, thread = one q row, kv tiles of 32.
// Stage buf (x2): K[32][64] | V[32][64] | pos[128][36]   (34816 B each)
// Scores: Ss[128][33] (single copy; intra-phase use only)
// ---------------------------------------------------------------------------
#define AT_K      0
#define AT_V      8192
#define AT_P      16384
#define AT_STAGE  34816                  // 8192+8192+18432
#define AT_SS     (2 * AT_STAGE)         // 69632
#define ATTN_SMEM (AT_SS + 128 * 33 * 4) // 86528

__global__ __launch_bounds__(128, 2)
void attn_kernel(const float* __restrict__ Qb, const float* __restrict__ KVb,
                 const float* __restrict__ pos, float* __restrict__ Ob)
{
    extern __shared__ char sm[];
    const uint32_t smb = smem_u32(sm);
    const int tid = threadIdx.x;
    const int b = blockIdx.z, h = blockIdx.y;
    const int q0 = blockIdx.x * 128;

    const float* Kbase   = KVb + (size_t)b * LKV * KVSTR + h * HDIM;
    const float* Vbase   = Kbase + DIMC;
    const float* posbase = pos + ((size_t)(h * LQ + q0)) * LKV;

    // Q row straight to registers (one-time, latency amortized)
    float Qr[64];
    {
        const float4* qrow = (const float4*)(Qb + ((size_t)(b * LQ + q0 + tid)) * DIMC + h * HDIM);
#pragma unroll
        for (int i = 0; i < 16; i++) {
            float4 t = qrow[i];
            Qr[4*i+0] = t.x; Qr[4*i+1] = t.y; Qr[4*i+2] = t.z; Qr[4*i+3] = t.w;
        }
    }

    float O[64];
#pragma unroll
    for (int d = 0; d < 64; d++) O[d] = 0.f;
    float mv = -1e30f, l = 0.f;

    // stage tile c into buf (c&1)
    auto stage = [&](int c) {
        const uint32_t sb = smb + (uint32_t)(c & 1) * AT_STAGE;
        const int kv0 = c * 32;
#pragma unroll
        for (int j = 0; j < 4; j++) {
            int q = tid + j * 128;            // 0..511
            int row = q >> 4, c16 = q & 15;
            cp16(sb + AT_K + row * 256 + c16 * 16, Kbase + (size_t)(kv0 + row) * KVSTR + c16 * 4);
            cp16(sb + AT_V + row * 256 + c16 * 16, Vbase + (size_t)(kv0 + row) * KVSTR + c16 * 4);
        }
#pragma unroll
        for (int j = 0; j < 8; j++) {
            int q = tid + j * 128;            // 0..1023
            int row = q >> 3, c16 = q & 7;
            cp16(sb + AT_P + row * 144 + c16 * 16, posbase + (size_t)row * LKV + kv0 + c16 * 4);
        }
        CP_COMMIT();
    };

    stage(0);

    float* Ss  = (float*)(sm + AT_SS);
    float* myS = Ss + tid * 33;

    const int NT = LKV / 32;   // 32
    for (int c = 0; c < NT; ++c) {
        __syncthreads();   // prior readers of buf[(c+1)&1] are done
        if (c + 1 < NT) {
            stage(c + 1);
            asm volatile("cp.async.wait_group 1;" ::: "memory");
        } else {
            asm volatile("cp.async.wait_group 0;" ::: "memory");
        }
        __syncthreads();   // staged data visible

        const char* sb = sm + (c & 1) * AT_STAGE;
        const float* Kb = (const float*)(sb + AT_K);
        const float* Vb = (const float*)(sb + AT_V);
        const float* Pb = (const float*)(sb + AT_P) + tid * 36;

        // pass 1: scores + running max
        float tmax = mv;
        float pa[4];
#pragma unroll 4
        for (int kv = 0; kv < 32; kv++) {
            if ((kv & 3) == 0) {
                float4 pq = *(const float4*)(Pb + kv);
                pa[0] = pq.x; pa[1] = pq.y; pa[2] = pq.z; pa[3] = pq.w;
            }
            const float4* kr = (const float4*)(Kb + kv * 64);
            float s0 = 0.f, s1 = 0.f, s2 = 0.f, s3 = 0.f;
#pragma unroll
            for (int d4 = 0; d4 < 16; d4++) {
                float4 kk = kr[d4];
                s0 += Qr[4 * d4 + 0] * kk.x;
                s1 += Qr[4 * d4 + 1] * kk.y;
                s2 += Qr[4 * d4 + 2] * kk.z;
                s3 += Qr[4 * d4 + 3] * kk.w;
            }
            float s = (s0 + s1) + (s2 + s3);
            s = s * SCALE + pa[kv & 3];
            myS[kv] = s;
            tmax = fmaxf(tmax, s);
        }

        // online softmax rescale
        float alpha = __expf(mv - tmax);
        mv = tmax;
        l *= alpha;
#pragma unroll
        for (int d = 0; d < 64; d++) O[d] *= alpha;

        // pass 2: exp + PV accumulate
        for (int kv = 0; kv < 32; kv++) {
            float p = __expf(myS[kv] - mv);
            l += p;
            const float4* vr = (const float4*)(Vb + kv * 64);
#pragma unroll
            for (int d4 = 0; d4 < 16; d4++) {
                float4 vv = vr[d4];
                O[4 * d4 + 0] += p * vv.x;
                O[4 * d4 + 1] += p * vv.y;
                O[4 * d4 + 2] += p * vv.z;
                O[4 * d4 + 3] += p * vv.w;
            }
        }
    }

    const float inv = 1.f / l;
    float4* orow = (float4*)(Ob + ((size_t)(b * LQ + q0 + tid)) * DIMC + h * HDIM);
#pragma unroll
    for (int d4 = 0; d4 < 16; d4++) {
        float4 v;
        v.x = O[4*d4+0] * inv; v.y = O[4*d4+1] * inv;
        v.z = O[4*d4+2] * inv; v.w = O[4*d4+3] * inv;
        orow[d4] = v;
    }
}

// ---------------------------------------------------------------------------
extern "C" void kernel_launch(void* const* d_in, const int* in_sizes, int n_in,
                              void* d_out, int out_size)
{
    (void)in_sizes; (void)n_in; (void)out_size;
    const float* q     = (const float*)d_in[0];
    const float* kv    = (const float*)d_in[1];
    const float* pos   = (const float*)d_in[2];
    const float* Wq    = (const float*)d_in[3];
    const float* Wkv   = (const float*)d_in[4];
    const float* Wproj = (const float*)d_in[5];
    const float* bproj = (const float*)d_in[6];
    float* out = (float*)d_out;

    float *gQ, *gKV, *gO;
    cudaGetSymbolAddress((void**)&gQ,  g_Q);
    cudaGetSymbolAddress((void**)&gKV, g_KV);
    cudaGetSymbolAddress((void**)&gO,  g_O);
    __nv_bfloat16 *qh, *ql, *kvh, *kvl, *oh, *ol, *wqh, *wql, *wkh, *wkl, *wph, *wpl;
    cudaGetSymbolAddress((void**)&qh,  g_qh);   cudaGetSymbolAddress((void**)&ql,  g_ql);
    cudaGetSymbolAddress((void**)&kvh, g_kvh);  cudaGetSymbolAddress((void**)&kvl, g_kvl);
    cudaGetSymbolAddress((void**)&oh,  g_oh);   cudaGetSymbolAddress((void**)&ol,  g_ol);
    cudaGetSymbolAddress((void**)&wqh, g_wqh);  cudaGetSymbolAddress((void**)&wql, g_wql);
    cudaGetSymbolAddress((void**)&wkh, g_wkh);  cudaGetSymbolAddress((void**)&wkl, g_wkl);
    cudaGetSymbolAddress((void**)&wph, g_wph);  cudaGetSymbolAddress((void**)&wpl, g_wpl);

    static bool attr_done = false;
    if (!attr_done) {
        cudaFuncSetAttribute(gemm_mma, cudaFuncAttributeMaxDynamicSharedMemorySize, 2 * STG_STRIDE);
        cudaFuncSetAttribute(attn_kernel, cudaFuncAttributeMaxDynamicSharedMemorySize, ATTN_SMEM);
        attr_done = true;
    }
    const int GEMM_SMEM = 2 * STG_STRIDE;

    const int M = MROWS;

    auto cvt = [](const float* p, __nv_bfloat16* h, __nv_bfloat16* l, size_t n) {
        int n4 = (int)(n / 4);
        cvt_split<<<(n4 + 255) / 256, 256>>>((const float4*)p, (uint2*)h, (uint2*)l, n4);
    };

    cvt(q,     qh,  ql,  (size_t)M * DIMC);
    cvt(kv,    kvh, kvl, (size_t)M * DIMC);
    cvt(Wq,    wqh, wql, (size_t)DIMC * DIMC);
    cvt(Wkv,   wkh, wkl, (size_t)2 * DIMC * DIMC);
    cvt(Wproj, wph, wpl, (size_t)DIMC * DIMC);

    gemm_mma<<<dim3(DIMC / 128, M / 128), 256, GEMM_SMEM>>>(qh, ql, wqh, wql, nullptr, gQ, DIMC, DIMC);
    gemm_mma<<<dim3(2 * DIMC / 128, M / 128), 256, GEMM_SMEM>>>(kvh, kvl, wkh, wkl, nullptr, gKV, 2 * DIMC, DIMC);
    attn_kernel<<<dim3(LQ / 128, NHEADS, BATCH), 128, ATTN_SMEM>>>(gQ, gKV, pos, gO);
    cvt(gO, oh, ol, (size_t)M * DIMC);
    gemm_mma<<<dim3(DIMC / 128, M / 128), 256, GEMM_SMEM>>>(oh, ol, wph, wpl, bproj, out, DIMC, DIMC);
}

// round 6
// speedup vs baseline: 2.1884x; 1.9620x over previous
#include <cuda_runtime.h>
#include <cuda_bf16.h>
#include <cstdint>
#include <cstddef>

// Problem constants
#define DIMC   768
#define NHEADS 12
#define HDIM   64
#define BATCH  8
#define LQ     1024
#define LKV    1024
#define SCALE  0.125f
#define KVSTR  (2 * DIMC)       // 1536 (elements)

#define MROWS  (BATCH * LQ)     // 8192

// bf16 split scratch
__device__ __nv_bfloat16 g_qh  [(size_t)MROWS * DIMC];      // input q split
__device__ __nv_bfloat16 g_ql  [(size_t)MROWS * DIMC];
__device__ __nv_bfloat16 g_kvh [(size_t)MROWS * DIMC];      // input kv split
__device__ __nv_bfloat16 g_kvl [(size_t)MROWS * DIMC];
__device__ __nv_bfloat16 g_wqh [(size_t)DIMC * DIMC];
__device__ __nv_bfloat16 g_wql [(size_t)DIMC * DIMC];
__device__ __nv_bfloat16 g_wkh [(size_t)2 * DIMC * DIMC];
__device__ __nv_bfloat16 g_wkl [(size_t)2 * DIMC * DIMC];
__device__ __nv_bfloat16 g_wph [(size_t)DIMC * DIMC];
__device__ __nv_bfloat16 g_wpl [(size_t)DIMC * DIMC];
// projected Q / KV, split (written by gemm epilogue)
__device__ __nv_bfloat16 g_PQh [(size_t)MROWS * DIMC];
__device__ __nv_bfloat16 g_PQl [(size_t)MROWS * DIMC];
__device__ __nv_bfloat16 g_PKh [(size_t)MROWS * 2 * DIMC];
__device__ __nv_bfloat16 g_PKl [(size_t)MROWS * 2 * DIMC];
// attention output, split (written by attn epilogue)
__device__ __nv_bfloat16 g_oh  [(size_t)MROWS * DIMC];
__device__ __nv_bfloat16 g_ol  [(size_t)MROWS * DIMC];

// ---------------------------------------------------------------------------
__device__ __forceinline__ uint32_t smem_u32(const void* p) {
    uint32_t a;
    asm("{ .reg .u64 t; cvta.to.shared.u64 t, %1; cvt.u32.u64 %0, t; }" : "=r"(a) : "l"(p));
    return a;
}
__device__ __forceinline__ void ldsm4(uint32_t* r, uint32_t addr) {
    asm volatile("ldmatrix.sync.aligned.m8n8.x4.shared.b16 {%0,%1,%2,%3}, [%4];"
        : "=r"(r[0]), "=r"(r[1]), "=r"(r[2]), "=r"(r[3]) : "r"(addr));
}
__device__ __forceinline__ void ldsm4t(uint32_t* r, uint32_t addr) {
    asm volatile("ldmatrix.sync.aligned.m8n8.x4.trans.shared.b16 {%0,%1,%2,%3}, [%4];"
        : "=r"(r[0]), "=r"(r[1]), "=r"(r[2]), "=r"(r[3]) : "r"(addr));
}
__device__ __forceinline__ void mma16816(float* d, const uint32_t* a, const uint32_t* b) {
    asm volatile("mma.sync.aligned.m16n8k16.row.col.f32.bf16.bf16.f32 "
        "{%0,%1,%2,%3}, {%4,%5,%6,%7}, {%8,%9}, {%0,%1,%2,%3};"
        : "+f"(d[0]), "+f"(d[1]), "+f"(d[2]), "+f"(d[3])
        : "r"(a[0]), "r"(a[1]), "r"(a[2]), "r"(a[3]), "r"(b[0]), "r"(b[1]));
}
__device__ __forceinline__ void cp16(uint32_t dst, const void* src) {
    asm volatile("cp.async.cg.shared.global [%0], [%1], 16;" :: "r"(dst), "l"(src) : "memory");
}
#define CP_COMMIT() asm volatile("cp.async.commit_group;" ::: "memory")

__device__ __forceinline__ uint32_t packbf(float a, float b) {
    __nv_bfloat162 t = __floats2bfloat162_rn(a, b);
    return *(uint32_t*)&t;
}

// swizzled byte offset inside a 128B-row tile
__device__ __forceinline__ uint32_t swz(int row, int c16) {
    return (uint32_t)(row * 128 + ((c16 ^ (row & 7)) << 4));
}

// stage one 128x64-bf16 buffer (16KB) via cp.async (per-thread 4x16B)
__device__ __forceinline__ void stage_buf(uint32_t sdst, const __nv_bfloat16* rowbase,
                                          int K, int k0, int crow, int chalf) {
    const __nv_bfloat16* src = rowbase + (size_t)crow * K + k0 + chalf * 8;
    uint32_t dbase = sdst + (uint32_t)crow * 128;
    int rx = crow & 7;
#pragma unroll
    for (int j = 0; j < 4; j++) {
        int c16 = chalf + j;
        cp16(dbase + (((c16 ^ rx)) << 4), src + j * 8);
    }
}

// ---------------------------------------------------------------------------
// C[M,N] = A[M,K] @ W[N,K]^T, bf16-split 3-pass via mma.sync.
// If Ch != null: write split bf16 (hi, lo) outputs. Else fp32 C (+bias).
// ---------------------------------------------------------------------------
#define STG_STRIDE 65536
#define BUF_AH 0
#define BUF_AL 16384
#define BUF_WH 32768
#define BUF_WL 49152

__global__ __launch_bounds__(256, 1)
void gemm_mma(const __nv_bfloat16* __restrict__ Ah, const __nv_bfloat16* __restrict__ Al,
              const __nv_bfloat16* __restrict__ Wh, const __nv_bfloat16* __restrict__ Wl,
              const float* __restrict__ bias, float* __restrict__ C,
              __nv_bfloat16* __restrict__ Ch, __nv_bfloat16* __restrict__ Cl,
              int N, int K)
{
    extern __shared__ char sm[];
    const uint32_t smb = smem_u32(sm);
    const int tid = threadIdx.x;
    const int wid = tid >> 5, lane = tid & 31;
    const int wm = wid >> 2, wn = wid & 3;
    const int m0 = blockIdx.y * 128, n0 = blockIdx.x * 128;

    const int crow = tid >> 1;
    const int chalf = (tid & 1) * 4;

    const __nv_bfloat16* Ahb = Ah + (size_t)m0 * K;
    const __nv_bfloat16* Alb = Al + (size_t)m0 * K;
    const __nv_bfloat16* Whb = Wh + (size_t)n0 * K;
    const __nv_bfloat16* Wlb = Wl + (size_t)n0 * K;

    const int g = lane >> 3, r = lane & 7;
    const int arl = (g & 1) * 8 + r;
    const int acs = g >> 1;
    const int brl = (g >> 1) * 8 + r;
    const int bcs = g & 1;

    float acc[4][4][4];
#pragma unroll
    for (int i = 0; i < 4; i++)
#pragma unroll
        for (int j = 0; j < 4; j++)
#pragma unroll
            for (int k = 0; k < 4; k++) acc[i][j][k] = 0.f;

    const int NC = K >> 6;

    {
        uint32_t sb = smb;
        stage_buf(sb + BUF_AH, Ahb, K, 0, crow, chalf);
        stage_buf(sb + BUF_AL, Alb, K, 0, crow, chalf);
        stage_buf(sb + BUF_WH, Whb, K, 0, crow, chalf);
        stage_buf(sb + BUF_WL, Wlb, K, 0, crow, chalf);
        CP_COMMIT();
    }

    for (int c = 0; c < NC; ++c) {
        if (c + 1 < NC) {
            uint32_t sb = smb + ((c + 1) & 1) * STG_STRIDE;
            int k0 = (c + 1) << 6;
            stage_buf(sb + BUF_AH, Ahb, K, k0, crow, chalf);
            stage_buf(sb + BUF_AL, Alb, K, k0, crow, chalf);
            stage_buf(sb + BUF_WH, Whb, K, k0, crow, chalf);
            stage_buf(sb + BUF_WL, Wlb, K, k0, crow, chalf);
            CP_COMMIT();
            asm volatile("cp.async.wait_group 1;" ::: "memory");
        } else {
            asm volatile("cp.async.wait_group 0;" ::: "memory");
        }
        __syncthreads();

        const uint32_t sb = smb + (c & 1) * STG_STRIDE;
        const uint32_t bAh = sb + BUF_AH, bAl = sb + BUF_AL;
        const uint32_t bWh = sb + BUF_WH, bWl = sb + BUF_WL;

#pragma unroll
        for (int s = 0; s < 4; ++s) {
            uint32_t afr[4][4], bh[2][4], bl[2][4];
#pragma unroll
            for (int mt = 0; mt < 4; ++mt)
                ldsm4(afr[mt], bAh + swz(wm * 64 + mt * 16 + arl, s * 2 + acs));
#pragma unroll
            for (int p = 0; p < 2; ++p)
                ldsm4(bh[p], bWh + swz(wn * 32 + p * 16 + brl, s * 2 + bcs));
#pragma unroll
            for (int p = 0; p < 2; ++p)
                ldsm4(bl[p], bWl + swz(wn * 32 + p * 16 + brl, s * 2 + bcs));

#pragma unroll
            for (int mt = 0; mt < 4; ++mt)
#pragma unroll
                for (int nt = 0; nt < 4; ++nt)
                    mma16816(acc[mt][nt], afr[mt], &bh[nt >> 1][(nt & 1) * 2]);
#pragma unroll
            for (int mt = 0; mt < 4; ++mt)
#pragma unroll
                for (int nt = 0; nt < 4; ++nt)
                    mma16816(acc[mt][nt], afr[mt], &bl[nt >> 1][(nt & 1) * 2]);
#pragma unroll
            for (int mt = 0; mt < 4; ++mt)
                ldsm4(afr[mt], bAl + swz(wm * 64 + mt * 16 + arl, s * 2 + acs));
#pragma unroll
            for (int mt = 0; mt < 4; ++mt)
#pragma unroll
                for (int nt = 0; nt < 4; ++nt)
                    mma16816(acc[mt][nt], afr[mt], &bh[nt >> 1][(nt & 1) * 2]);
        }
        __syncthreads();
    }

    const int er = lane >> 2, ec = (lane & 3) * 2;
    if (Ch) {
        // split bf16 output
#pragma unroll
        for (int mt = 0; mt < 4; ++mt) {
#pragma unroll
            for (int nt = 0; nt < 4; ++nt) {
                int grow = m0 + wm * 64 + mt * 16 + er;
                int gcol = n0 + wn * 32 + nt * 8 + ec;
#pragma unroll
                for (int rr = 0; rr < 2; ++rr) {
                    float v0 = acc[mt][nt][rr * 2 + 0];
                    float v1 = acc[mt][nt][rr * 2 + 1];
                    __nv_bfloat16 h0 = __float2bfloat16_rn(v0);
                    __nv_bfloat16 h1 = __float2bfloat16_rn(v1);
                    float l0f = v0 - __bfloat162float(h0);
                    float l1f = v1 - __bfloat162float(h1);
                    size_t off = (size_t)(grow + rr * 8) * N + gcol;
                    *(uint32_t*)(Ch + off) = packbf(__bfloat162float(h0), __bfloat162float(h1));
                    *(uint32_t*)(Cl + off) = packbf(l0f, l1f);
                }
            }
        }
    } else {
#pragma unroll
        for (int mt = 0; mt < 4; ++mt) {
#pragma unroll
            for (int nt = 0; nt < 4; ++nt) {
                int grow = m0 + wm * 64 + mt * 16 + er;
                int gcol = n0 + wn * 32 + nt * 8 + ec;
                float b0 = 0.f, b1 = 0.f;
                if (bias) { b0 = bias[gcol]; b1 = bias[gcol + 1]; }
                float2 v0 = make_float2(acc[mt][nt][0] + b0, acc[mt][nt][1] + b1);
                float2 v1 = make_float2(acc[mt][nt][2] + b0, acc[mt][nt][3] + b1);
                *(float2*)(C + (size_t)grow * N + gcol) = v0;
                *(float2*)(C + (size_t)(grow + 8) * N + gcol) = v1;
            }
        }
    }
}

// ---------------------------------------------------------------------------
// fp32 -> (hi, lo) bf16 split, vectorized x4
// ---------------------------------------------------------------------------
__global__ __launch_bounds__(256)
void cvt_split(const float4* __restrict__ in, uint2* __restrict__ hi,
               uint2* __restrict__ lo, int n4)
{
    int i = blockIdx.x * blockDim.x + threadIdx.x;
    if (i >= n4) return;
    float4 x = in[i];
    __nv_bfloat162 h01 = __floats2bfloat162_rn(x.x, x.y);
    __nv_bfloat162 h23 = __floats2bfloat162_rn(x.z, x.w);
    float r0 = x.x - __low2float(h01), r1 = x.y - __high2float(h01);
    float r2 = x.z - __low2float(h23), r3 = x.w - __high2float(h23);
    __nv_bfloat162 l01 = __floats2bfloat162_rn(r0, r1);
    __nv_bfloat162 l23 = __floats2bfloat162_rn(r2, r3);
    hi[i] = make_uint2(*(uint32_t*)&h01, *(uint32_t*)&h23);
    lo[i] = make_uint2(*(uint32_t*)&l01, *(uint32_t*)&l23);
}

// ---------------------------------------------------------------------------
// Tensor-core flash attention, bf16-split.
// Grid (LQ/128, H, B), 256 threads (8 warps), warp = 16 q-rows, kv tiles of 64.
// smem: Qh|Ql (32KB) + 2 stage bufs { Kh,Kl,Vh,Vl (8KB each), pos (36864B) }
// ---------------------------------------------------------------------------
#define AQ_H     0
#define AQ_L     16384
#define AST_BASE 32768
#define AST_KH   0
#define AST_KL   8192
#define AST_VH   16384
#define AST_VL   24576
#define AST_P    32768
#define AST_SIZE 69632                    // 32768 + 36864
#define ATTN_SMEM (AST_BASE + 2 * AST_SIZE)   // 172032

__global__ __launch_bounds__(256)
void attn_mma(const __nv_bfloat16* __restrict__ Qh, const __nv_bfloat16* __restrict__ Ql,
              const __nv_bfloat16* __restrict__ KVh, const __nv_bfloat16* __restrict__ KVl,
              const float* __restrict__ pos,
              __nv_bfloat16* __restrict__ Oh, __nv_bfloat16* __restrict__ Ol)
{
    extern __shared__ char sm[];
    const uint32_t smb = smem_u32(sm);
    const int tid = threadIdx.x, wid = tid >> 5, lane = tid & 31;
    const int b = blockIdx.z, h = blockIdx.y;
    const int q0 = blockIdx.x * 128;

    const int g = lane >> 3, r = lane & 7;
    const int arl = (g & 1) * 8 + r, acs = g >> 1;
    const int brl = (g >> 1) * 8 + r, bcs = g & 1;
    const int er = lane >> 2, ec = (lane & 3) * 2;

    // ---- stage Q tile (hi/lo) once: 128 rows x 64 bf16 each ----
    const size_t qrow0 = (size_t)(b * LQ + q0);
    for (int i = tid; i < 128 * 8; i += 256) {
        int row = i >> 3, c16 = i & 7;
        size_t off = (qrow0 + row) * DIMC + h * HDIM + c16 * 8;
        uint32_t d = swz(row, c16);
        cp16(smb + AQ_H + d, Qh + off);
        cp16(smb + AQ_L + d, Ql + off);
    }
    CP_COMMIT();

    const float* posbase = pos + ((size_t)(h * LQ + q0)) * LKV;

    // stage kv tile c into buf (c&1): K/V hi/lo + pos
    auto stage = [&](int c) {
        const uint32_t sb = smb + AST_BASE + (uint32_t)(c & 1) * AST_SIZE;
        const int kv0 = c * 64;
        const size_t kvrow0 = (size_t)(b * LKV + kv0);
        for (int i = tid; i < 64 * 8; i += 256) {
            int row = i >> 3, c16 = i & 7;
            size_t off = (kvrow0 + row) * KVSTR + h * HDIM + c16 * 8;
            uint32_t d = swz(row, c16);
            cp16(sb + AST_KH + d, KVh + off);
            cp16(sb + AST_KL + d, KVl + off);
            cp16(sb + AST_VH + d, KVh + off + DIMC);
            cp16(sb + AST_VL + d, KVl + off + DIMC);
        }
        for (int i = tid; i < 2048; i += 256) {
            int row = i >> 4, c16 = i & 15;
            cp16(sb + AST_P + row * 288 + c16 * 16, posbase + (size_t)row * LKV + kv0 + c16 * 4);
        }
        CP_COMMIT();
    };

    float O[8][4];
#pragma unroll
    for (int nt = 0; nt < 8; nt++)
#pragma unroll
        for (int j = 0; j < 4; j++) O[nt][j] = 0.f;
    float mv0 = -1e30f, mv1 = -1e30f, l0 = 0.f, l1 = 0.f;

    stage(0);

    const int NT = LKV / 64;   // 16
    for (int c = 0; c < NT; ++c) {
        __syncthreads();   // readers of buf (c+1)&1 done
        if (c + 1 < NT) {
            stage(c + 1);
            asm volatile("cp.async.wait_group 1;" ::: "memory");
        } else {
            asm volatile("cp.async.wait_group 0;" ::: "memory");
        }
        __syncthreads();

        const uint32_t sb = smb + AST_BASE + (uint32_t)(c & 1) * AST_SIZE;

        // ---- init S accumulator with 8*pos (so final *SCALE gives QK*0.125 + pos) ----
        float acc[8][4];
        {
            const char* pB = sm + AST_BASE + (size_t)(c & 1) * AST_SIZE + AST_P
                           + (wid * 16 + er) * 288 + ec * 4;
#pragma unroll
            for (int nt = 0; nt < 8; nt++) {
                float2 p0 = *(const float2*)(pB + nt * 32);
                float2 p1 = *(const float2*)(pB + nt * 32 + 8 * 288);
                acc[nt][0] = 8.f * p0.x; acc[nt][1] = 8.f * p0.y;
                acc[nt][2] = 8.f * p1.x; acc[nt][3] = 8.f * p1.y;
            }
        }

        // ---- S = Q K^T (3-pass split) ----
        {
            const uint32_t qbh = smb + AQ_H, qbl = smb + AQ_L;
            const uint32_t kbh = sb + AST_KH, kbl = sb + AST_KL;
#pragma unroll
            for (int ks = 0; ks < 4; ks++) {
                uint32_t qf_h[4], qf_l[4], kh[4][4], kl[4][4];
                ldsm4(qf_h, qbh + swz(wid * 16 + arl, ks * 2 + acs));
                ldsm4(qf_l, qbl + swz(wid * 16 + arl, ks * 2 + acs));
#pragma unroll
                for (int p = 0; p < 4; p++) {
                    ldsm4(kh[p], kbh + swz(p * 16 + brl, ks * 2 + bcs));
                    ldsm4(kl[p], kbl + swz(p * 16 + brl, ks * 2 + bcs));
                }
#pragma unroll
                for (int nt = 0; nt < 8; nt++)
                    mma16816(acc[nt], qf_h, &kh[nt >> 1][(nt & 1) * 2]);
#pragma unroll
                for (int nt = 0; nt < 8; nt++)
                    mma16816(acc[nt], qf_h, &kl[nt >> 1][(nt & 1) * 2]);
#pragma unroll
                for (int nt = 0; nt < 8; nt++)
                    mma16816(acc[nt], qf_l, &kh[nt >> 1][(nt & 1) * 2]);
            }
        }

        // ---- online softmax on fragments ----
        float tmax0 = mv0, tmax1 = mv1;
#pragma unroll
        for (int nt = 0; nt < 8; nt++) {
            acc[nt][0] *= SCALE; acc[nt][1] *= SCALE;
            acc[nt][2] *= SCALE; acc[nt][3] *= SCALE;
            tmax0 = fmaxf(tmax0, fmaxf(acc[nt][0], acc[nt][1]));
            tmax1 = fmaxf(tmax1, fmaxf(acc[nt][2], acc[nt][3]));
        }
        tmax0 = fmaxf(tmax0, __shfl_xor_sync(0xffffffffu, tmax0, 1));
        tmax0 = fmaxf(tmax0, __shfl_xor_sync(0xffffffffu, tmax0, 2));
        tmax1 = fmaxf(tmax1, __shfl_xor_sync(0xffffffffu, tmax1, 1));
        tmax1 = fmaxf(tmax1, __shfl_xor_sync(0xffffffffu, tmax1, 2));

        float alpha0 = __expf(mv0 - tmax0);
        float alpha1 = __expf(mv1 - tmax1);
        mv0 = tmax0; mv1 = tmax1;

        uint32_t pa_h[4][4], pa_l[4][4];
        float la0 = 0.f, la1 = 0.f;
#pragma unroll
        for (int nt = 0; nt < 8; nt++) {
            float p0 = __expf(acc[nt][0] - mv0);
            float p1 = __expf(acc[nt][1] - mv0);
            float p2 = __expf(acc[nt][2] - mv1);
            float p3 = __expf(acc[nt][3] - mv1);
            la0 += p0 + p1; la1 += p2 + p3;
            __nv_bfloat162 h01 = __floats2bfloat162_rn(p0, p1);
            __nv_bfloat162 h23 = __floats2bfloat162_rn(p2, p3);
            float q0f = p0 - __low2float(h01), q1f = p1 - __high2float(h01);
            float q2f = p2 - __low2float(h23), q3f = p3 - __high2float(h23);
            int t = nt >> 1, base = (nt & 1) * 2;
            pa_h[t][base + 0] = *(uint32_t*)&h01;
            pa_h[t][base + 1] = *(uint32_t*)&h23;
            pa_l[t][base + 0] = packbf(q0f, q1f);
            pa_l[t][base + 1] = packbf(q2f, q3f);
        }
        l0 = l0 * alpha0 + la0;
        l1 = l1 * alpha1 + la1;

#pragma unroll
        for (int nt = 0; nt < 8; nt++) {
            O[nt][0] *= alpha0; O[nt][1] *= alpha0;
            O[nt][2] *= alpha1; O[nt][3] *= alpha1;
        }

        // ---- O += P V (3-pass split), V via trans ldmatrix ----
        {
            const uint32_t vbh = sb + AST_VH, vbl = sb + AST_VL;
#pragma unroll
            for (int ks = 0; ks < 4; ks++) {
                uint32_t vh[4][4], vl[4][4];
#pragma unroll
                for (int tp = 0; tp < 4; tp++) {
                    ldsm4t(vh[tp], vbh + swz(ks * 16 + arl, tp * 2 + acs));
                    ldsm4t(vl[tp], vbl + swz(ks * 16 + arl, tp * 2 + acs));
                }
#pragma unroll
                for (int nt = 0; nt < 8; nt++)
                    mma16816(O[nt], pa_h[ks], &vh[nt >> 1][(nt & 1) * 2]);
#pragma unroll
                for (int nt = 0; nt < 8; nt++)
                    mma16816(O[nt], pa_h[ks], &vl[nt >> 1][(nt & 1) * 2]);
#pragma unroll
                for (int nt = 0; nt < 8; nt++)
                    mma16816(O[nt], pa_l[ks], &vh[nt >> 1][(nt & 1) * 2]);
            }
        }
    }

    // ---- epilogue: normalize + split-store ----
    l0 += __shfl_xor_sync(0xffffffffu, l0, 1);
    l0 += __shfl_xor_sync(0xffffffffu, l0, 2);
    l1 += __shfl_xor_sync(0xffffffffu, l1, 1);
    l1 += __shfl_xor_sync(0xffffffffu, l1, 2);
    float inv0 = 1.f / l0, inv1 = 1.f / l1;

    const size_t row0 = (size_t)(b * LQ + q0 + wid * 16 + er);
#pragma unroll
    for (int nt = 0; nt < 8; nt++) {
        int col = h * HDIM + nt * 8 + ec;
        float v0 = O[nt][0] * inv0, v1 = O[nt][1] * inv0;
        float v2 = O[nt][2] * inv1, v3 = O[nt][3] * inv1;
        __nv_bfloat162 h01 = __floats2bfloat162_rn(v0, v1);
        __nv_bfloat162 h23 = __floats2bfloat162_rn(v2, v3);
        float q0f = v0 - __low2float(h01), q1f = v1 - __high2float(h01);
        float q2f = v2 - __low2float(h23), q3f = v3 - __high2float(h23);
        size_t offA = row0 * DIMC + col;
        size_t offB = (row0 + 8) * DIMC + col;
        *(uint32_t*)(Oh + offA) = *(uint32_t*)&h01;
        *(uint32_t*)(Ol + offA) = packbf(q0f, q1f);
        *(uint32_t*)(Oh + offB) = *(uint32_t*)&h23;
        *(uint32_t*)(Ol + offB) = packbf(q2f, q3f);
    }
}

// ---------------------------------------------------------------------------
extern "C" void kernel_launch(void* const* d_in, const int* in_sizes, int n_in,
                              void* d_out, int out_size)
{
    (void)in_sizes; (void)n_in; (void)out_size;
    const float* q     = (const float*)d_in[0];
    const float* kv    = (const float*)d_in[1];
    const float* pos   = (const float*)d_in[2];
    const float* Wq    = (const float*)d_in[3];
    const float* Wkv   = (const float*)d_in[4];
    const float* Wproj = (const float*)d_in[5];
    const float* bproj = (const float*)d_in[6];
    float* out = (float*)d_out;

    __nv_bfloat16 *qh, *ql, *kvh, *kvl, *wqh, *wql, *wkh, *wkl, *wph, *wpl;
    __nv_bfloat16 *PQh, *PQl, *PKh, *PKl, *oh, *ol;
    cudaGetSymbolAddress((void**)&qh,  g_qh);   cudaGetSymbolAddress((void**)&ql,  g_ql);
    cudaGetSymbolAddress((void**)&kvh, g_kvh);  cudaGetSymbolAddress((void**)&kvl, g_kvl);
    cudaGetSymbolAddress((void**)&wqh, g_wqh);  cudaGetSymbolAddress((void**)&wql, g_wql);
    cudaGetSymbolAddress((void**)&wkh, g_wkh);  cudaGetSymbolAddress((void**)&wkl, g_wkl);
    cudaGetSymbolAddress((void**)&wph, g_wph);  cudaGetSymbolAddress((void**)&wpl, g_wpl);
    cudaGetSymbolAddress((void**)&PQh, g_PQh);  cudaGetSymbolAddress((void**)&PQl, g_PQl);
    cudaGetSymbolAddress((void**)&PKh, g_PKh);  cudaGetSymbolAddress((void**)&PKl, g_PKl);
    cudaGetSymbolAddress((void**)&oh,  g_oh);   cudaGetSymbolAddress((void**)&ol,  g_ol);

    static bool attr_done = false;
    if (!attr_done) {
        cudaFuncSetAttribute(gemm_mma, cudaFuncAttributeMaxDynamicSharedMemorySize, 2 * STG_STRIDE);
        cudaFuncSetAttribute(attn_mma, cudaFuncAttributeMaxDynamicSharedMemorySize, ATTN_SMEM);
        attr_done = true;
    }
    const int GEMM_SMEM = 2 * STG_STRIDE;

    const int M = MROWS;

    auto cvt = [](const float* p, __nv_bfloat16* hh, __nv_bfloat16* ll, size_t n) {
        int n4 = (int)(n / 4);
        cvt_split<<<(n4 + 255) / 256, 256>>>((const float4*)p, (uint2*)hh, (uint2*)ll, n4);
    };

    cvt(q,     qh,  ql,  (size_t)M * DIMC);
    cvt(kv,    kvh, kvl, (size_t)M * DIMC);
    cvt(Wq,    wqh, wql, (size_t)DIMC * DIMC);
    cvt(Wkv,   wkh, wkl, (size_t)2 * DIMC * DIMC);
    cvt(Wproj, wph, wpl, (size_t)DIMC * DIMC);

    // projections -> split bf16 outputs
    gemm_mma<<<dim3(DIMC / 128, M / 128), 256, GEMM_SMEM>>>(
        qh, ql, wqh, wql, nullptr, nullptr, PQh, PQl, DIMC, DIMC);
    gemm_mma<<<dim3(2 * DIMC / 128, M / 128), 256, GEMM_SMEM>>>(
        kvh, kvl, wkh, wkl, nullptr, nullptr, PKh, PKl, 2 * DIMC, DIMC);

    // tensor-core flash attention -> split bf16 O
    attn_mma<<<dim3(LQ / 128, NHEADS, BATCH), 256, ATTN_SMEM>>>(
        PQh, PQl, PKh, PKl, pos, oh, ol);

    // output projection (fp32 + bias)
    gemm_mma<<<dim3(DIMC / 128, M / 128), 256, GEMM_SMEM>>>(
        oh, ol, wph, wpl, bproj, out, nullptr, nullptr, DIMC, DIMC);
}

// round 7
// speedup vs baseline: 2.5955x; 1.1860x over previous
#include <cuda_runtime.h>
#include <cuda_bf16.h>
#include <cstdint>
#include <cstddef>

// Problem constants
#define DIMC   768
#define NHEADS 12
#define HDIM   64
#define BATCH  8
#define LQ     1024
#define LKV    1024
#define SCALE  0.125f
#define KVSTR  (2 * DIMC)       // 1536 (elements)

#define MROWS  (BATCH * LQ)     // 8192

// bf16 split scratch
__device__ __nv_bfloat16 g_qh  [(size_t)MROWS * DIMC];
__device__ __nv_bfloat16 g_ql  [(size_t)MROWS * DIMC];
__device__ __nv_bfloat16 g_kvh [(size_t)MROWS * DIMC];
__device__ __nv_bfloat16 g_kvl [(size_t)MROWS * DIMC];
__device__ __nv_bfloat16 g_wqh [(size_t)DIMC * DIMC];
__device__ __nv_bfloat16 g_wql [(size_t)DIMC * DIMC];
__device__ __nv_bfloat16 g_wkh [(size_t)2 * DIMC * DIMC];
__device__ __nv_bfloat16 g_wkl [(size_t)2 * DIMC * DIMC];
__device__ __nv_bfloat16 g_wph [(size_t)DIMC * DIMC];
__device__ __nv_bfloat16 g_wpl [(size_t)DIMC * DIMC];
__device__ __nv_bfloat16 g_PQh [(size_t)MROWS * DIMC];
__device__ __nv_bfloat16 g_PQl [(size_t)MROWS * DIMC];
__device__ __nv_bfloat16 g_PKh [(size_t)MROWS * 2 * DIMC];
__device__ __nv_bfloat16 g_PKl [(size_t)MROWS * 2 * DIMC];
__device__ __nv_bfloat16 g_oh  [(size_t)MROWS * DIMC];
__device__ __nv_bfloat16 g_ol  [(size_t)MROWS * DIMC];

// ---------------------------------------------------------------------------
__device__ __forceinline__ uint32_t smem_u32(const void* p) {
    uint32_t a;
    asm("{ .reg .u64 t; cvta.to.shared.u64 t, %1; cvt.u32.u64 %0, t; }" : "=r"(a) : "l"(p));
    return a;
}
__device__ __forceinline__ void ldsm4(uint32_t* r, uint32_t addr) {
    asm volatile("ldmatrix.sync.aligned.m8n8.x4.shared.b16 {%0,%1,%2,%3}, [%4];"
        : "=r"(r[0]), "=r"(r[1]), "=r"(r[2]), "=r"(r[3]) : "r"(addr));
}
__device__ __forceinline__ void ldsm4t(uint32_t* r, uint32_t addr) {
    asm volatile("ldmatrix.sync.aligned.m8n8.x4.trans.shared.b16 {%0,%1,%2,%3}, [%4];"
        : "=r"(r[0]), "=r"(r[1]), "=r"(r[2]), "=r"(r[3]) : "r"(addr));
}
__device__ __forceinline__ void mma16816(float* d, const uint32_t* a, const uint32_t* b) {
    asm volatile("mma.sync.aligned.m16n8k16.row.col.f32.bf16.bf16.f32 "
        "{%0,%1,%2,%3}, {%4,%5,%6,%7}, {%8,%9}, {%0,%1,%2,%3};"
        : "+f"(d[0]), "+f"(d[1]), "+f"(d[2]), "+f"(d[3])
        : "r"(a[0]), "r"(a[1]), "r"(a[2]), "r"(a[3]), "r"(b[0]), "r"(b[1]));
}
__device__ __forceinline__ void cp16(uint32_t dst, const void* src) {
    asm volatile("cp.async.cg.shared.global [%0], [%1], 16;" :: "r"(dst), "l"(src) : "memory");
}
#define CP_COMMIT() asm volatile("cp.async.commit_group;" ::: "memory")

__device__ __forceinline__ uint32_t packbf(float a, float b) {
    __nv_bfloat162 t = __floats2bfloat162_rn(a, b);
    return *(uint32_t*)&t;
}

// swizzled byte offset inside a 128B-row tile
__device__ __forceinline__ uint32_t swz(int row, int c16) {
    return (uint32_t)(row * 128 + ((c16 ^ (row & 7)) << 4));
}

// ---------------------------------------------------------------------------
// GEMM core: C[M,N] = A @ W^T, bf16-split 3-pass, 512 threads, warp 32x32.
// ---------------------------------------------------------------------------
#define STG_STRIDE 65536
#define BUF_AH 0
#define BUF_AL 16384
#define BUF_WH 32768
#define BUF_WL 49152

// stage one 128x64-bf16 buffer (16KB) with 512 threads (2 cp16/thread)
__device__ __forceinline__ void stage_buf512(uint32_t sdst, const __nv_bfloat16* rowbase,
                                             int K, int k0, int tid) {
#pragma unroll
    for (int rep = 0; rep < 2; rep++) {
        int i = tid + rep * 512;            // 0..1023
        int row = i >> 3, c16 = i & 7;
        cp16(sdst + swz(row, c16), rowbase + (size_t)row * K + k0 + c16 * 8);
    }
}

// device-side gemm body (shared by combined and proj kernels)
__device__ __forceinline__
void gemm_body(const __nv_bfloat16* __restrict__ Ah, const __nv_bfloat16* __restrict__ Al,
               const __nv_bfloat16* __restrict__ Wh, const __nv_bfloat16* __restrict__ Wl,
               const float* __restrict__ bias, float* __restrict__ C,
               __nv_bfloat16* __restrict__ Ch, __nv_bfloat16* __restrict__ Cl,
               int N, int K, int m0, int n0, char* sm)
{
    const uint32_t smb = smem_u32(sm);
    const int tid = threadIdx.x;
    const int wid = tid >> 5, lane = tid & 31;
    const int wm = wid >> 2, wn = wid & 3;          // 4x4 warp grid, warp = 32x32

    const __nv_bfloat16* Ahb = Ah + (size_t)m0 * K;
    const __nv_bfloat16* Alb = Al + (size_t)m0 * K;
    const __nv_bfloat16* Whb = Wh + (size_t)n0 * K;
    const __nv_bfloat16* Wlb = Wl + (size_t)n0 * K;

    const int g = lane >> 3, r = lane & 7;
    const int arl = (g & 1) * 8 + r;
    const int acs = g >> 1;
    const int brl = (g >> 1) * 8 + r;
    const int bcs = g & 1;

    float acc[2][4][4];
#pragma unroll
    for (int i = 0; i < 2; i++)
#pragma unroll
        for (int j = 0; j < 4; j++)
#pragma unroll
            for (int k = 0; k < 4; k++) acc[i][j][k] = 0.f;

    const int NC = K >> 6;

    {
        uint32_t sb = smb;
        stage_buf512(sb + BUF_AH, Ahb, K, 0, tid);
        stage_buf512(sb + BUF_AL, Alb, K, 0, tid);
        stage_buf512(sb + BUF_WH, Whb, K, 0, tid);
        stage_buf512(sb + BUF_WL, Wlb, K, 0, tid);
        CP_COMMIT();
    }

    for (int c = 0; c < NC; ++c) {
        if (c + 1 < NC) {
            uint32_t sb = smb + ((c + 1) & 1) * STG_STRIDE;
            int k0 = (c + 1) << 6;
            stage_buf512(sb + BUF_AH, Ahb, K, k0, tid);
            stage_buf512(sb + BUF_AL, Alb, K, k0, tid);
            stage_buf512(sb + BUF_WH, Whb, K, k0, tid);
            stage_buf512(sb + BUF_WL, Wlb, K, k0, tid);
            CP_COMMIT();
            asm volatile("cp.async.wait_group 1;" ::: "memory");
        } else {
            asm volatile("cp.async.wait_group 0;" ::: "memory");
        }
        __syncthreads();

        const uint32_t sb = smb + (c & 1) * STG_STRIDE;
        const uint32_t bAh = sb + BUF_AH, bAl = sb + BUF_AL;
        const uint32_t bWh = sb + BUF_WH, bWl = sb + BUF_WL;

#pragma unroll
        for (int s = 0; s < 4; ++s) {
            uint32_t ah[2][4], al[2][4], bh[2][4], bl[2][4];
#pragma unroll
            for (int mt = 0; mt < 2; ++mt) {
                ldsm4(ah[mt], bAh + swz(wm * 32 + mt * 16 + arl, s * 2 + acs));
                ldsm4(al[mt], bAl + swz(wm * 32 + mt * 16 + arl, s * 2 + acs));
            }
#pragma unroll
            for (int p = 0; p < 2; ++p) {
                ldsm4(bh[p], bWh + swz(wn * 32 + p * 16 + brl, s * 2 + bcs));
                ldsm4(bl[p], bWl + swz(wn * 32 + p * 16 + brl, s * 2 + bcs));
            }
#pragma unroll
            for (int mt = 0; mt < 2; ++mt)
#pragma unroll
                for (int nt = 0; nt < 4; ++nt)
                    mma16816(acc[mt][nt], ah[mt], &bh[nt >> 1][(nt & 1) * 2]);
#pragma unroll
            for (int mt = 0; mt < 2; ++mt)
#pragma unroll
                for (int nt = 0; nt < 4; ++nt)
                    mma16816(acc[mt][nt], ah[mt], &bl[nt >> 1][(nt & 1) * 2]);
#pragma unroll
            for (int mt = 0; mt < 2; ++mt)
#pragma unroll
                for (int nt = 0; nt < 4; ++nt)
                    mma16816(acc[mt][nt], al[mt], &bh[nt >> 1][(nt & 1) * 2]);
        }
        __syncthreads();
    }

    const int er = lane >> 2, ec = (lane & 3) * 2;
    if (Ch) {
#pragma unroll
        for (int mt = 0; mt < 2; ++mt) {
#pragma unroll
            for (int nt = 0; nt < 4; ++nt) {
                int grow = m0 + wm * 32 + mt * 16 + er;
                int gcol = n0 + wn * 32 + nt * 8 + ec;
#pragma unroll
                for (int rr = 0; rr < 2; ++rr) {
                    float v0 = acc[mt][nt][rr * 2 + 0];
                    float v1 = acc[mt][nt][rr * 2 + 1];
                    __nv_bfloat16 h0 = __float2bfloat16_rn(v0);
                    __nv_bfloat16 h1 = __float2bfloat16_rn(v1);
                    float l0f = v0 - __bfloat162float(h0);
                    float l1f = v1 - __bfloat162float(h1);
                    size_t off = (size_t)(grow + rr * 8) * N + gcol;
                    *(uint32_t*)(Ch + off) = packbf(__bfloat162float(h0), __bfloat162float(h1));
                    *(uint32_t*)(Cl + off) = packbf(l0f, l1f);
                }
            }
        }
    } else {
#pragma unroll
        for (int mt = 0; mt < 2; ++mt) {
#pragma unroll
            for (int nt = 0; nt < 4; ++nt) {
                int grow = m0 + wm * 32 + mt * 16 + er;
                int gcol = n0 + wn * 32 + nt * 8 + ec;
                float b0 = 0.f, b1 = 0.f;
                if (bias) { b0 = bias[gcol]; b1 = bias[gcol + 1]; }
                float2 v0 = make_float2(acc[mt][nt][0] + b0, acc[mt][nt][1] + b1);
                float2 v1 = make_float2(acc[mt][nt][2] + b0, acc[mt][nt][3] + b1);
                *(float2*)(C + (size_t)grow * N + gcol) = v0;
                *(float2*)(C + (size_t)(grow + 8) * N + gcol) = v1;
            }
        }
    }
}

// Combined Q + KV projection gemm. 1-D grid: [0,384) Q tiles, [384,1152) KV tiles.
__global__ __launch_bounds__(512, 1)
void gemm_qkv(const __nv_bfloat16* __restrict__ qh, const __nv_bfloat16* __restrict__ ql,
              const __nv_bfloat16* __restrict__ wqh, const __nv_bfloat16* __restrict__ wql,
              __nv_bfloat16* __restrict__ PQh, __nv_bfloat16* __restrict__ PQl,
              const __nv_bfloat16* __restrict__ kvh, const __nv_bfloat16* __restrict__ kvl,
              const __nv_bfloat16* __restrict__ wkh, const __nv_bfloat16* __restrict__ wkl,
              __nv_bfloat16* __restrict__ PKh, __nv_bfloat16* __restrict__ PKl)
{
    extern __shared__ char sm[];
    int bx = blockIdx.x;
    if (bx < 384) {
        int nb = bx % 6, mb = bx / 6;
        gemm_body(qh, ql, wqh, wql, nullptr, nullptr, PQh, PQl,
                  DIMC, DIMC, mb * 128, nb * 128, sm);
    } else {
        int t = bx - 384;
        int nb = t % 12, mb = t / 12;
        gemm_body(kvh, kvl, wkh, wkl, nullptr, nullptr, PKh, PKl,
                  2 * DIMC, DIMC, mb * 128, nb * 128, sm);
    }
}

// Output projection gemm (fp32 out + bias)
__global__ __launch_bounds__(512, 1)
void gemm_proj(const __nv_bfloat16* __restrict__ oh, const __nv_bfloat16* __restrict__ ol,
               const __nv_bfloat16* __restrict__ wph, const __nv_bfloat16* __restrict__ wpl,
               const float* __restrict__ bias, float* __restrict__ out)
{
    extern __shared__ char sm[];
    int nb = blockIdx.x % 6, mb = blockIdx.x / 6;
    gemm_body(oh, ol, wph, wpl, bias, out, nullptr, nullptr,
              DIMC, DIMC, mb * 128, nb * 128, sm);
}

// ---------------------------------------------------------------------------
// One merged fp32 -> (hi,lo) bf16 split over all 5 input arrays.
// Segments (float4 units), compile-time sizes.
// ---------------------------------------------------------------------------
#define N4_Q   ((size_t)MROWS * DIMC / 4)           // 1572864
#define N4_W1  ((size_t)DIMC * DIMC / 4)            // 147456
#define N4_W2  ((size_t)2 * DIMC * DIMC / 4)        // 294912
#define N4_TOT (N4_Q + N4_Q + N4_W1 + N4_W2 + N4_W1)

__global__ __launch_bounds__(256)
void cvt_all(const float4* __restrict__ q,   uint2* __restrict__ qh,  uint2* __restrict__ ql,
             const float4* __restrict__ kv,  uint2* __restrict__ kvh, uint2* __restrict__ kvl,
             const float4* __restrict__ wq,  uint2* __restrict__ wqh, uint2* __restrict__ wql,
             const float4* __restrict__ wkv, uint2* __restrict__ wkh, uint2* __restrict__ wkl,
             const float4* __restrict__ wp,  uint2* __restrict__ wph, uint2* __restrict__ wpl)
{
    size_t i = (size_t)blockIdx.x * blockDim.x + threadIdx.x;
    if (i >= N4_TOT) return;
    const float4* src; uint2 *hi, *lo; size_t j = i;
    if (j < N4_Q)                 { src = q;   hi = qh;  lo = ql;  }
    else if ((j -= N4_Q) < N4_Q)  { src = kv;  hi = kvh; lo = kvl; }
    else if ((j -= N4_Q) < N4_W1) { src = wq;  hi = wqh; lo = wql; }
    else if ((j -= N4_W1) < N4_W2){ src = wkv; hi = wkh; lo = wkl; }
    else { j -= N4_W2;              src = wp;  hi = wph; lo = wpl; }

    float4 x = src[j];
    __nv_bfloat162 h01 = __floats2bfloat162_rn(x.x, x.y);
    __nv_bfloat162 h23 = __floats2bfloat162_rn(x.z, x.w);
    float r0 = x.x - __low2float(h01), r1 = x.y - __high2float(h01);
    float r2 = x.z - __low2float(h23), r3 = x.w - __high2float(h23);
    __nv_bfloat162 l01 = __floats2bfloat162_rn(r0, r1);
    __nv_bfloat162 l23 = __floats2bfloat162_rn(r2, r3);
    hi[j] = make_uint2(*(uint32_t*)&h01, *(uint32_t*)&h23);
    lo[j] = make_uint2(*(uint32_t*)&l01, *(uint32_t*)&l23);
}

// ---------------------------------------------------------------------------
// Tensor-core flash attention, bf16-split (unchanged from R6).
// ---------------------------------------------------------------------------
#define AQ_H     0
#define AQ_L     16384
#define AST_BASE 32768
#define AST_KH   0
#define AST_KL   8192
#define AST_VH   16384
#define AST_VL   24576
#define AST_P    32768
#define AST_SIZE 69632
#define ATTN_SMEM (AST_BASE + 2 * AST_SIZE)   // 172032

__global__ __launch_bounds__(256)
void attn_mma(const __nv_bfloat16* __restrict__ Qh, const __nv_bfloat16* __restrict__ Ql,
              const __nv_bfloat16* __restrict__ KVh, const __nv_bfloat16* __restrict__ KVl,
              const float* __restrict__ pos,
              __nv_bfloat16* __restrict__ Oh, __nv_bfloat16* __restrict__ Ol)
{
    extern __shared__ char sm[];
    const uint32_t smb = smem_u32(sm);
    const int tid = threadIdx.x, wid = tid >> 5, lane = tid & 31;
    const int b = blockIdx.z, h = blockIdx.y;
    const int q0 = blockIdx.x * 128;

    const int g = lane >> 3, r = lane & 7;
    const int arl = (g & 1) * 8 + r, acs = g >> 1;
    const int brl = (g >> 1) * 8 + r, bcs = g & 1;
    const int er = lane >> 2, ec = (lane & 3) * 2;

    const size_t qrow0 = (size_t)(b * LQ + q0);
    for (int i = tid; i < 128 * 8; i += 256) {
        int row = i >> 3, c16 = i & 7;
        size_t off = (qrow0 + row) * DIMC + h * HDIM + c16 * 8;
        uint32_t d = swz(row, c16);
        cp16(smb + AQ_H + d, Qh + off);
        cp16(smb + AQ_L + d, Ql + off);
    }
    CP_COMMIT();

    const float* posbase = pos + ((size_t)(h * LQ + q0)) * LKV;

    auto stage = [&](int c) {
        const uint32_t sb = smb + AST_BASE + (uint32_t)(c & 1) * AST_SIZE;
        const int kv0 = c * 64;
        const size_t kvrow0 = (size_t)(b * LKV + kv0);
        for (int i = tid; i < 64 * 8; i += 256) {
            int row = i >> 3, c16 = i & 7;
            size_t off = (kvrow0 + row) * KVSTR + h * HDIM + c16 * 8;
            uint32_t d = swz(row, c16);
            cp16(sb + AST_KH + d, KVh + off);
            cp16(sb + AST_KL + d, KVl + off);
            cp16(sb + AST_VH + d, KVh + off + DIMC);
            cp16(sb + AST_VL + d, KVl + off + DIMC);
        }
        for (int i = tid; i < 2048; i += 256) {
            int row = i >> 4, c16 = i & 15;
            cp16(sb + AST_P + row * 288 + c16 * 16, posbase + (size_t)row * LKV + kv0 + c16 * 4);
        }
        CP_COMMIT();
    };

    float O[8][4];
#pragma unroll
    for (int nt = 0; nt < 8; nt++)
#pragma unroll
        for (int j = 0; j < 4; j++) O[nt][j] = 0.f;
    float mv0 = -1e30f, mv1 = -1e30f, l0 = 0.f, l1 = 0.f;

    stage(0);

    const int NT = LKV / 64;
    for (int c = 0; c < NT; ++c) {
        __syncthreads();
        if (c + 1 < NT) {
            stage(c + 1);
            asm volatile("cp.async.wait_group 1;" ::: "memory");
        } else {
            asm volatile("cp.async.wait_group 0;" ::: "memory");
        }
        __syncthreads();

        const uint32_t sb = smb + AST_BASE + (uint32_t)(c & 1) * AST_SIZE;

        float acc[8][4];
        {
            const char* pB = sm + AST_BASE + (size_t)(c & 1) * AST_SIZE + AST_P
                           + (wid * 16 + er) * 288 + ec * 4;
#pragma unroll
            for (int nt = 0; nt < 8; nt++) {
                float2 p0 = *(const float2*)(pB + nt * 32);
                float2 p1 = *(const float2*)(pB + nt * 32 + 8 * 288);
                acc[nt][0] = 8.f * p0.x; acc[nt][1] = 8.f * p0.y;
                acc[nt][2] = 8.f * p1.x; acc[nt][3] = 8.f * p1.y;
            }
        }

        {
            const uint32_t qbh = smb + AQ_H, qbl = smb + AQ_L;
            const uint32_t kbh = sb + AST_KH, kbl = sb + AST_KL;
#pragma unroll
            for (int ks = 0; ks < 4; ks++) {
                uint32_t qf_h[4], qf_l[4], kh[4][4], kl[4][4];
                ldsm4(qf_h, qbh + swz(wid * 16 + arl, ks * 2 + acs));
                ldsm4(qf_l, qbl + swz(wid * 16 + arl, ks * 2 + acs));
#pragma unroll
                for (int p = 0; p < 4; p++) {
                    ldsm4(kh[p], kbh + swz(p * 16 + brl, ks * 2 + bcs));
                    ldsm4(kl[p], kbl + swz(p * 16 + brl, ks * 2 + bcs));
                }
#pragma unroll
                for (int nt = 0; nt < 8; nt++)
                    mma16816(acc[nt], qf_h, &kh[nt >> 1][(nt & 1) * 2]);
#pragma unroll
                for (int nt = 0; nt < 8; nt++)
                    mma16816(acc[nt], qf_h, &kl[nt >> 1][(nt & 1) * 2]);
#pragma unroll
                for (int nt = 0; nt < 8; nt++)
                    mma16816(acc[nt], qf_l, &kh[nt >> 1][(nt & 1) * 2]);
            }
        }

        float tmax0 = mv0, tmax1 = mv1;
#pragma unroll
        for (int nt = 0; nt < 8; nt++) {
            acc[nt][0] *= SCALE; acc[nt][1] *= SCALE;
            acc[nt][2] *= SCALE; acc[nt][3] *= SCALE;
            tmax0 = fmaxf(tmax0, fmaxf(acc[nt][0], acc[nt][1]));
            tmax1 = fmaxf(tmax1, fmaxf(acc[nt][2], acc[nt][3]));
        }
        tmax0 = fmaxf(tmax0, __shfl_xor_sync(0xffffffffu, tmax0, 1));
        tmax0 = fmaxf(tmax0, __shfl_xor_sync(0xffffffffu, tmax0, 2));
        tmax1 = fmaxf(tmax1, __shfl_xor_sync(0xffffffffu, tmax1, 1));
        tmax1 = fmaxf(tmax1, __shfl_xor_sync(0xffffffffu, tmax1, 2));

        float alpha0 = __expf(mv0 - tmax0);
        float alpha1 = __expf(mv1 - tmax1);
        mv0 = tmax0; mv1 = tmax1;

        uint32_t pa_h[4][4], pa_l[4][4];
        float la0 = 0.f, la1 = 0.f;
#pragma unroll
        for (int nt = 0; nt < 8; nt++) {
            float p0 = __expf(acc[nt][0] - mv0);
            float p1 = __expf(acc[nt][1] - mv0);
            float p2 = __expf(acc[nt][2] - mv1);
            float p3 = __expf(acc[nt][3] - mv1);
            la0 += p0 + p1; la1 += p2 + p3;
            __nv_bfloat162 h01 = __floats2bfloat162_rn(p0, p1);
            __nv_bfloat162 h23 = __floats2bfloat162_rn(p2, p3);
            float q0f = p0 - __low2float(h01), q1f = p1 - __high2float(h01);
            float q2f = p2 - __low2float(h23), q3f = p3 - __high2float(h23);
            int t = nt >> 1, base = (nt & 1) * 2;
            pa_h[t][base + 0] = *(uint32_t*)&h01;
            pa_h[t][base + 1] = *(uint32_t*)&h23;
            pa_l[t][base + 0] = packbf(q0f, q1f);
            pa_l[t][base + 1] = packbf(q2f, q3f);
        }
        l0 = l0 * alpha0 + la0;
        l1 = l1 * alpha1 + la1;

#pragma unroll
        for (int nt = 0; nt < 8; nt++) {
            O[nt][0] *= alpha0; O[nt][1] *= alpha0;
            O[nt][2] *= alpha1; O[nt][3] *= alpha1;
        }

        {
            const uint32_t vbh = sb + AST_VH, vbl = sb + AST_VL;
#pragma unroll
            for (int ks = 0; ks < 4; ks++) {
                uint32_t vh[4][4], vl[4][4];
#pragma unroll
                for (int tp = 0; tp < 4; tp++) {
                    ldsm4t(vh[tp], vbh + swz(ks * 16 + arl, tp * 2 + acs));
                    ldsm4t(vl[tp], vbl + swz(ks * 16 + arl, tp * 2 + acs));
                }
#pragma unroll
                for (int nt = 0; nt < 8; nt++)
                    mma16816(O[nt], pa_h[ks], &vh[nt >> 1][(nt & 1) * 2]);
#pragma unroll
                for (int nt = 0; nt < 8; nt++)
                    mma16816(O[nt], pa_h[ks], &vl[nt >> 1][(nt & 1) * 2]);
#pragma unroll
                for (int nt = 0; nt < 8; nt++)
                    mma16816(O[nt], pa_l[ks], &vh[nt >> 1][(nt & 1) * 2]);
            }
        }
    }

    l0 += __shfl_xor_sync(0xffffffffu, l0, 1);
    l0 += __shfl_xor_sync(0xffffffffu, l0, 2);
    l1 += __shfl_xor_sync(0xffffffffu, l1, 1);
    l1 += __shfl_xor_sync(0xffffffffu, l1, 2);
    float inv0 = 1.f / l0, inv1 = 1.f / l1;

    const size_t row0 = (size_t)(b * LQ + q0 + wid * 16 + er);
#pragma unroll
    for (int nt = 0; nt < 8; nt++) {
        int col = h * HDIM + nt * 8 + ec;
        float v0 = O[nt][0] * inv0, v1 = O[nt][1] * inv0;
        float v2 = O[nt][2] * inv1, v3 = O[nt][3] * inv1;
        __nv_bfloat162 h01 = __floats2bfloat162_rn(v0, v1);
        __nv_bfloat162 h23 = __floats2bfloat162_rn(v2, v3);
        float q0f = v0 - __low2float(h01), q1f = v1 - __high2float(h01);
        float q2f = v2 - __low2float(h23), q3f = v3 - __high2float(h23);
        size_t offA = row0 * DIMC + col;
        size_t offB = (row0 + 8) * DIMC + col;
        *(uint32_t*)(Oh + offA) = *(uint32_t*)&h01;
        *(uint32_t*)(Ol + offA) = packbf(q0f, q1f);
        *(uint32_t*)(Oh + offB) = *(uint32_t*)&h23;
        *(uint32_t*)(Ol + offB) = packbf(q2f, q3f);
    }
}

// ---------------------------------------------------------------------------
extern "C" void kernel_launch(void* const* d_in, const int* in_sizes, int n_in,
                              void* d_out, int out_size)
{
    (void)in_sizes; (void)n_in; (void)out_size;
    const float* q     = (const float*)d_in[0];
    const float* kv    = (const float*)d_in[1];
    const float* pos   = (const float*)d_in[2];
    const float* Wq    = (const float*)d_in[3];
    const float* Wkv   = (const float*)d_in[4];
    const float* Wproj = (const float*)d_in[5];
    const float* bproj = (const float*)d_in[6];
    float* out = (float*)d_out;

    __nv_bfloat16 *qh, *ql, *kvh, *kvl, *wqh, *wql, *wkh, *wkl, *wph, *wpl;
    __nv_bfloat16 *PQh, *PQl, *PKh, *PKl, *oh, *ol;
    cudaGetSymbolAddress((void**)&qh,  g_qh);   cudaGetSymbolAddress((void**)&ql,  g_ql);
    cudaGetSymbolAddress((void**)&kvh, g_kvh);  cudaGetSymbolAddress((void**)&kvl, g_kvl);
    cudaGetSymbolAddress((void**)&wqh, g_wqh);  cudaGetSymbolAddress((void**)&wql, g_wql);
    cudaGetSymbolAddress((void**)&wkh, g_wkh);  cudaGetSymbolAddress((void**)&wkl, g_wkl);
    cudaGetSymbolAddress((void**)&wph, g_wph);  cudaGetSymbolAddress((void**)&wpl, g_wpl);
    cudaGetSymbolAddress((void**)&PQh, g_PQh);  cudaGetSymbolAddress((void**)&PQl, g_PQl);
    cudaGetSymbolAddress((void**)&PKh, g_PKh);  cudaGetSymbolAddress((void**)&PKl, g_PKl);
    cudaGetSymbolAddress((void**)&oh,  g_oh);   cudaGetSymbolAddress((void**)&ol,  g_ol);

    static bool attr_done = false;
    if (!attr_done) {
        cudaFuncSetAttribute(gemm_qkv,  cudaFuncAttributeMaxDynamicSharedMemorySize, 2 * STG_STRIDE);
        cudaFuncSetAttribute(gemm_proj, cudaFuncAttributeMaxDynamicSharedMemorySize, 2 * STG_STRIDE);
        cudaFuncSetAttribute(attn_mma,  cudaFuncAttributeMaxDynamicSharedMemorySize, ATTN_SMEM);
        attr_done = true;
    }
    const int GEMM_SMEM = 2 * STG_STRIDE;

    // one merged split kernel for all fp32 inputs
    {
        int grid = (int)((N4_TOT + 255) / 256);
        cvt_all<<<grid, 256>>>(
            (const float4*)q,   (uint2*)qh,  (uint2*)ql,
            (const float4*)kv,  (uint2*)kvh, (uint2*)kvl,
            (const float4*)Wq,  (uint2*)wqh, (uint2*)wql,
            (const float4*)Wkv, (uint2*)wkh, (uint2*)wkl,
            (const float4*)Wproj, (uint2*)wph, (uint2*)wpl);
    }

    // combined Q + KV projections -> split bf16
    gemm_qkv<<<1152, 512, GEMM_SMEM>>>(qh, ql, wqh, wql, PQh, PQl,
                                       kvh, kvl, wkh, wkl, PKh, PKl);

    // tensor-core flash attention -> split bf16 O
    attn_mma<<<dim3(LQ / 128, NHEADS, BATCH), 256, ATTN_SMEM>>>(
        PQh, PQl, PKh, PKl, pos, oh, ol);

    // output projection (fp32 + bias)
    gemm_proj<<<384, 512, GEMM_SMEM>>>(oh, ol, wph, wpl, bproj, out);
}

// round 8
// speedup vs baseline: 2.7433x; 1.0570x over previous
#include <cuda_runtime.h>
#include <cuda_bf16.h>
#include <cstdint>
#include <cstddef>

// Problem constants
#define DIMC   768
#define NHEADS 12
#define HDIM   64
#define BATCH  8
#define LQ     1024
#define LKV    1024
#define SCALE  0.125f
#define KVSTR  (2 * DIMC)       // 1536 (elements)

#define MROWS  (BATCH * LQ)     // 8192

// bf16 split scratch
__device__ __nv_bfloat16 g_qh  [(size_t)MROWS * DIMC];
__device__ __nv_bfloat16 g_ql  [(size_t)MROWS * DIMC];
__device__ __nv_bfloat16 g_kvh [(size_t)MROWS * DIMC];
__device__ __nv_bfloat16 g_kvl [(size_t)MROWS * DIMC];
__device__ __nv_bfloat16 g_wqh [(size_t)DIMC * DIMC];
__device__ __nv_bfloat16 g_wql [(size_t)DIMC * DIMC];
__device__ __nv_bfloat16 g_wkh [(size_t)2 * DIMC * DIMC];
__device__ __nv_bfloat16 g_wkl [(size_t)2 * DIMC * DIMC];
__device__ __nv_bfloat16 g_wph [(size_t)DIMC * DIMC];
__device__ __nv_bfloat16 g_wpl [(size_t)DIMC * DIMC];
__device__ __nv_bfloat16 g_PQh [(size_t)MROWS * DIMC];
__device__ __nv_bfloat16 g_PQl [(size_t)MROWS * DIMC];
__device__ __nv_bfloat16 g_PKh [(size_t)MROWS * 2 * DIMC];
__device__ __nv_bfloat16 g_PKl [(size_t)MROWS * 2 * DIMC];
__device__ __nv_bfloat16 g_oh  [(size_t)MROWS * DIMC];
__device__ __nv_bfloat16 g_ol  [(size_t)MROWS * DIMC];

// ---------------------------------------------------------------------------
__device__ __forceinline__ uint32_t smem_u32(const void* p) {
    uint32_t a;
    asm("{ .reg .u64 t; cvta.to.shared.u64 t, %1; cvt.u32.u64 %0, t; }" : "=r"(a) : "l"(p));
    return a;
}
__device__ __forceinline__ void ldsm4(uint32_t* r, uint32_t addr) {
    asm volatile("ldmatrix.sync.aligned.m8n8.x4.shared.b16 {%0,%1,%2,%3}, [%4];"
        : "=r"(r[0]), "=r"(r[1]), "=r"(r[2]), "=r"(r[3]) : "r"(addr));
}
__device__ __forceinline__ void ldsm4t(uint32_t* r, uint32_t addr) {
    asm volatile("ldmatrix.sync.aligned.m8n8.x4.trans.shared.b16 {%0,%1,%2,%3}, [%4];"
        : "=r"(r[0]), "=r"(r[1]), "=r"(r[2]), "=r"(r[3]) : "r"(addr));
}
__device__ __forceinline__ void mma16816(float* d, const uint32_t* a, const uint32_t* b) {
    asm volatile("mma.sync.aligned.m16n8k16.row.col.f32.bf16.bf16.f32 "
        "{%0,%1,%2,%3}, {%4,%5,%6,%7}, {%8,%9}, {%0,%1,%2,%3};"
        : "+f"(d[0]), "+f"(d[1]), "+f"(d[2]), "+f"(d[3])
        : "r"(a[0]), "r"(a[1]), "r"(a[2]), "r"(a[3]), "r"(b[0]), "r"(b[1]));
}
__device__ __forceinline__ void cp16(uint32_t dst, const void* src) {
    asm volatile("cp.async.cg.shared.global [%0], [%1], 16;" :: "r"(dst), "l"(src) : "memory");
}
#define CP_COMMIT() asm volatile("cp.async.commit_group;" ::: "memory")

__device__ __forceinline__ uint32_t packbf(float a, float b) {
    __nv_bfloat162 t = __floats2bfloat162_rn(a, b);
    return *(uint32_t*)&t;
}

// swizzled byte offset inside a 128B-row tile
__device__ __forceinline__ uint32_t swz(int row, int c16) {
    return (uint32_t)(row * 128 + ((c16 ^ (row & 7)) << 4));
}

// ---------------------------------------------------------------------------
// GEMM core: tile 128(M)x64(N), 256 threads, warp 32x32 (4x2 warp grid),
// K-chunks of 64, 2-stage cp.async, 2 CTAs/SM.
// ---------------------------------------------------------------------------
#define GSTG   49152          // stage stride: AH 16K | AL 16K | WH 8K | WL 8K
#define GB_AH  0
#define GB_AL  16384
#define GB_WH  32768
#define GB_WL  40960
#define GEMM_SMEM (2 * GSTG)  // 98304

// stage A chunk: 128 rows x 64 bf16 = 1024 16B lines (4 per thread)
__device__ __forceinline__ void stageA(uint32_t sdst, const __nv_bfloat16* rowbase,
                                       int K, int k0, int tid) {
#pragma unroll
    for (int rep = 0; rep < 4; rep++) {
        int i = tid + rep * 256;
        int row = i >> 3, c16 = i & 7;
        cp16(sdst + swz(row, c16), rowbase + (size_t)row * K + k0 + c16 * 8);
    }
}
// stage W chunk: 64 rows x 64 bf16 = 512 16B lines (2 per thread)
__device__ __forceinline__ void stageW(uint32_t sdst, const __nv_bfloat16* rowbase,
                                       int K, int k0, int tid) {
#pragma unroll
    for (int rep = 0; rep < 2; rep++) {
        int i = tid + rep * 256;
        int row = i >> 3, c16 = i & 7;
        cp16(sdst + swz(row, c16), rowbase + (size_t)row * K + k0 + c16 * 8);
    }
}

__device__ __forceinline__
void gemm_body(const __nv_bfloat16* __restrict__ Ah, const __nv_bfloat16* __restrict__ Al,
               const __nv_bfloat16* __restrict__ Wh, const __nv_bfloat16* __restrict__ Wl,
               const float* __restrict__ bias, float* __restrict__ C,
               __nv_bfloat16* __restrict__ Ch, __nv_bfloat16* __restrict__ Cl,
               int N, int K, int m0, int n0, char* sm)
{
    const uint32_t smb = smem_u32(sm);
    const int tid = threadIdx.x;
    const int wid = tid >> 5, lane = tid & 31;
    const int wm = wid >> 1, wn = wid & 1;          // 4x2 warp grid, warp = 32x32

    const __nv_bfloat16* Ahb = Ah + (size_t)m0 * K;
    const __nv_bfloat16* Alb = Al + (size_t)m0 * K;
    const __nv_bfloat16* Whb = Wh + (size_t)n0 * K;
    const __nv_bfloat16* Wlb = Wl + (size_t)n0 * K;

    const int g = lane >> 3, r = lane & 7;
    const int arl = (g & 1) * 8 + r;
    const int acs = g >> 1;
    const int brl = (g >> 1) * 8 + r;
    const int bcs = g & 1;

    float acc[2][4][4];
#pragma unroll
    for (int i = 0; i < 2; i++)
#pragma unroll
        for (int j = 0; j < 4; j++)
#pragma unroll
            for (int k = 0; k < 4; k++) acc[i][j][k] = 0.f;

    const int NC = K >> 6;   // 12

    {
        uint32_t sb = smb;
        stageA(sb + GB_AH, Ahb, K, 0, tid);
        stageA(sb + GB_AL, Alb, K, 0, tid);
        stageW(sb + GB_WH, Whb, K, 0, tid);
        stageW(sb + GB_WL, Wlb, K, 0, tid);
        CP_COMMIT();
    }

    for (int c = 0; c < NC; ++c) {
        if (c + 1 < NC) {
            uint32_t sb = smb + ((c + 1) & 1) * GSTG;
            int k0 = (c + 1) << 6;
            stageA(sb + GB_AH, Ahb, K, k0, tid);
            stageA(sb + GB_AL, Alb, K, k0, tid);
            stageW(sb + GB_WH, Whb, K, k0, tid);
            stageW(sb + GB_WL, Wlb, K, k0, tid);
            CP_COMMIT();
            asm volatile("cp.async.wait_group 1;" ::: "memory");
        } else {
            asm volatile("cp.async.wait_group 0;" ::: "memory");
        }
        __syncthreads();

        const uint32_t sb = smb + (c & 1) * GSTG;
        const uint32_t bAh = sb + GB_AH, bAl = sb + GB_AL;
        const uint32_t bWh = sb + GB_WH, bWl = sb + GB_WL;

#pragma unroll
        for (int s = 0; s < 4; ++s) {
            uint32_t ah[2][4], al[2][4], bh[2][4], bl[2][4];
#pragma unroll
            for (int mt = 0; mt < 2; ++mt) {
                ldsm4(ah[mt], bAh + swz(wm * 32 + mt * 16 + arl, s * 2 + acs));
                ldsm4(al[mt], bAl + swz(wm * 32 + mt * 16 + arl, s * 2 + acs));
            }
#pragma unroll
            for (int p = 0; p < 2; ++p) {
                ldsm4(bh[p], bWh + swz(wn * 32 + p * 16 + brl, s * 2 + bcs));
                ldsm4(bl[p], bWl + swz(wn * 32 + p * 16 + brl, s * 2 + bcs));
            }
#pragma unroll
            for (int mt = 0; mt < 2; ++mt)
#pragma unroll
                for (int nt = 0; nt < 4; ++nt)
                    mma16816(acc[mt][nt], ah[mt], &bh[nt >> 1][(nt & 1) * 2]);
#pragma unroll
            for (int mt = 0; mt < 2; ++mt)
#pragma unroll
                for (int nt = 0; nt < 4; ++nt)
                    mma16816(acc[mt][nt], ah[mt], &bl[nt >> 1][(nt & 1) * 2]);
#pragma unroll
            for (int mt = 0; mt < 2; ++mt)
#pragma unroll
                for (int nt = 0; nt < 4; ++nt)
                    mma16816(acc[mt][nt], al[mt], &bh[nt >> 1][(nt & 1) * 2]);
        }
        __syncthreads();
    }

    const int er = lane >> 2, ec = (lane & 3) * 2;
    if (Ch) {
#pragma unroll
        for (int mt = 0; mt < 2; ++mt) {
#pragma unroll
            for (int nt = 0; nt < 4; ++nt) {
                int grow = m0 + wm * 32 + mt * 16 + er;
                int gcol = n0 + wn * 32 + nt * 8 + ec;
#pragma unroll
                for (int rr = 0; rr < 2; ++rr) {
                    float v0 = acc[mt][nt][rr * 2 + 0];
                    float v1 = acc[mt][nt][rr * 2 + 1];
                    __nv_bfloat16 h0 = __float2bfloat16_rn(v0);
                    __nv_bfloat16 h1 = __float2bfloat16_rn(v1);
                    float l0f = v0 - __bfloat162float(h0);
                    float l1f = v1 - __bfloat162float(h1);
                    size_t off = (size_t)(grow + rr * 8) * N + gcol;
                    *(uint32_t*)(Ch + off) = packbf(__bfloat162float(h0), __bfloat162float(h1));
                    *(uint32_t*)(Cl + off) = packbf(l0f, l1f);
                }
            }
        }
    } else {
#pragma unroll
        for (int mt = 0; mt < 2; ++mt) {
#pragma unroll
            for (int nt = 0; nt < 4; ++nt) {
                int grow = m0 + wm * 32 + mt * 16 + er;
                int gcol = n0 + wn * 32 + nt * 8 + ec;
                float b0 = 0.f, b1 = 0.f;
                if (bias) { b0 = bias[gcol]; b1 = bias[gcol + 1]; }
                float2 v0 = make_float2(acc[mt][nt][0] + b0, acc[mt][nt][1] + b1);
                float2 v1 = make_float2(acc[mt][nt][2] + b0, acc[mt][nt][3] + b1);
                *(float2*)(C + (size_t)grow * N + gcol) = v0;
                *(float2*)(C + (size_t)(grow + 8) * N + gcol) = v1;
            }
        }
    }
}

// Combined Q + KV projection gemm. Grid: [0,768) Q tiles (64m x 12n),
// [768, 2304) KV tiles (64m x 24n).
__global__ __launch_bounds__(256, 2)
void gemm_qkv(const __nv_bfloat16* __restrict__ qh, const __nv_bfloat16* __restrict__ ql,
              const __nv_bfloat16* __restrict__ wqh, const __nv_bfloat16* __restrict__ wql,
              __nv_bfloat16* __restrict__ PQh, __nv_bfloat16* __restrict__ PQl,
              const __nv_bfloat16* __restrict__ kvh, const __nv_bfloat16* __restrict__ kvl,
              const __nv_bfloat16* __restrict__ wkh, const __nv_bfloat16* __restrict__ wkl,
              __nv_bfloat16* __restrict__ PKh, __nv_bfloat16* __restrict__ PKl)
{
    extern __shared__ char sm[];
    int bx = blockIdx.x;
    if (bx < 768) {
        int nb = bx % 12, mb = bx / 12;
        gemm_body(qh, ql, wqh, wql, nullptr, nullptr, PQh, PQl,
                  DIMC, DIMC, mb * 128, nb * 64, sm);
    } else {
        int t = bx - 768;
        int nb = t % 24, mb = t / 24;
        gemm_body(kvh, kvl, wkh, wkl, nullptr, nullptr, PKh, PKl,
                  2 * DIMC, DIMC, mb * 128, nb * 64, sm);
    }
}

// Output projection gemm (fp32 out + bias). Grid 768 (64m x 12n).
__global__ __launch_bounds__(256, 2)
void gemm_proj(const __nv_bfloat16* __restrict__ oh, const __nv_bfloat16* __restrict__ ol,
               const __nv_bfloat16* __restrict__ wph, const __nv_bfloat16* __restrict__ wpl,
               const float* __restrict__ bias, float* __restrict__ out)
{
    extern __shared__ char sm[];
    int nb = blockIdx.x % 12, mb = blockIdx.x / 12;
    gemm_body(oh, ol, wph, wpl, bias, out, nullptr, nullptr,
              DIMC, DIMC, mb * 128, nb * 64, sm);
}

// ---------------------------------------------------------------------------
// One merged fp32 -> (hi,lo) bf16 split over all 5 input arrays.
// ---------------------------------------------------------------------------
#define N4_Q   ((size_t)MROWS * DIMC / 4)
#define N4_W1  ((size_t)DIMC * DIMC / 4)
#define N4_W2  ((size_t)2 * DIMC * DIMC / 4)
#define N4_TOT (N4_Q + N4_Q + N4_W1 + N4_W2 + N4_W1)

__global__ __launch_bounds__(256)
void cvt_all(const float4* __restrict__ q,   uint2* __restrict__ qh,  uint2* __restrict__ ql,
             const float4* __restrict__ kv,  uint2* __restrict__ kvh, uint2* __restrict__ kvl,
             const float4* __restrict__ wq,  uint2* __restrict__ wqh, uint2* __restrict__ wql,
             const float4* __restrict__ wkv, uint2* __restrict__ wkh, uint2* __restrict__ wkl,
             const float4* __restrict__ wp,  uint2* __restrict__ wph, uint2* __restrict__ wpl)
{
    size_t i = (size_t)blockIdx.x * blockDim.x + threadIdx.x;
    if (i >= N4_TOT) return;
    const float4* src; uint2 *hi, *lo; size_t j = i;
    if (j < N4_Q)                 { src = q;   hi = qh;  lo = ql;  }
    else if ((j -= N4_Q) < N4_Q)  { src = kv;  hi = kvh; lo = kvl; }
    else if ((j -= N4_Q) < N4_W1) { src = wq;  hi = wqh; lo = wql; }
    else if ((j -= N4_W1) < N4_W2){ src = wkv; hi = wkh; lo = wkl; }
    else { j -= N4_W2;              src = wp;  hi = wph; lo = wpl; }

    float4 x = src[j];
    __nv_bfloat162 h01 = __floats2bfloat162_rn(x.x, x.y);
    __nv_bfloat162 h23 = __floats2bfloat162_rn(x.z, x.w);
    float r0 = x.x - __low2float(h01), r1 = x.y - __high2float(h01);
    float r2 = x.z - __low2float(h23), r3 = x.w - __high2float(h23);
    __nv_bfloat162 l01 = __floats2bfloat162_rn(r0, r1);
    __nv_bfloat162 l23 = __floats2bfloat162_rn(r2, r3);
    hi[j] = make_uint2(*(uint32_t*)&h01, *(uint32_t*)&h23);
    lo[j] = make_uint2(*(uint32_t*)&l01, *(uint32_t*)&l23);
}

// ---------------------------------------------------------------------------
// Tensor-core flash attention, bf16-split (unchanged from R7).
// ---------------------------------------------------------------------------
#define AQ_H     0
#define AQ_L     16384
#define AST_BASE 32768
#define AST_KH   0
#define AST_KL   8192
#define AST_VH   16384
#define AST_VL   24576
#define AST_P    32768
#define AST_SIZE 69632
#define ATTN_SMEM (AST_BASE + 2 * AST_SIZE)   // 172032

__global__ __launch_bounds__(256)
void attn_mma(const __nv_bfloat16* __restrict__ Qh, const __nv_bfloat16* __restrict__ Ql,
              const __nv_bfloat16* __restrict__ KVh, const __nv_bfloat16* __restrict__ KVl,
              const float* __restrict__ pos,
              __nv_bfloat16* __restrict__ Oh, __nv_bfloat16* __restrict__ Ol)
{
    extern __shared__ char sm[];
    const uint32_t smb = smem_u32(sm);
    const int tid = threadIdx.x, wid = tid >> 5, lane = tid & 31;
    const int b = blockIdx.z, h = blockIdx.y;
    const int q0 = blockIdx.x * 128;

    const int g = lane >> 3, r = lane & 7;
    const int arl = (g & 1) * 8 + r, acs = g >> 1;
    const int brl = (g >> 1) * 8 + r, bcs = g & 1;
    const int er = lane >> 2, ec = (lane & 3) * 2;

    const size_t qrow0 = (size_t)(b * LQ + q0);
    for (int i = tid; i < 128 * 8; i += 256) {
        int row = i >> 3, c16 = i & 7;
        size_t off = (qrow0 + row) * DIMC + h * HDIM + c16 * 8;
        uint32_t d = swz(row, c16);
        cp16(smb + AQ_H + d, Qh + off);
        cp16(smb + AQ_L + d, Ql + off);
    }
    CP_COMMIT();

    const float* posbase = pos + ((size_t)(h * LQ + q0)) * LKV;

    auto stage = [&](int c) {
        const uint32_t sb = smb + AST_BASE + (uint32_t)(c & 1) * AST_SIZE;
        const int kv0 = c * 64;
        const size_t kvrow0 = (size_t)(b * LKV + kv0);
        for (int i = tid; i < 64 * 8; i += 256) {
            int row = i >> 3, c16 = i & 7;
            size_t off = (kvrow0 + row) * KVSTR + h * HDIM + c16 * 8;
            uint32_t d = swz(row, c16);
            cp16(sb + AST_KH + d, KVh + off);
            cp16(sb + AST_KL + d, KVl + off);
            cp16(sb + AST_VH + d, KVh + off + DIMC);
            cp16(sb + AST_VL + d, KVl + off + DIMC);
        }
        for (int i = tid; i < 2048; i += 256) {
            int row = i >> 4, c16 = i & 15;
            cp16(sb + AST_P + row * 288 + c16 * 16, posbase + (size_t)row * LKV + kv0 + c16 * 4);
        }
        CP_COMMIT();
    };

    float O[8][4];
#pragma unroll
    for (int nt = 0; nt < 8; nt++)
#pragma unroll
        for (int j = 0; j < 4; j++) O[nt][j] = 0.f;
    float mv0 = -1e30f, mv1 = -1e30f, l0 = 0.f, l1 = 0.f;

    stage(0);

    const int NT = LKV / 64;
    for (int c = 0; c < NT; ++c) {
        __syncthreads();
        if (c + 1 < NT) {
            stage(c + 1);
            asm volatile("cp.async.wait_group 1;" ::: "memory");
        } else {
            asm volatile("cp.async.wait_group 0;" ::: "memory");
        }
        __syncthreads();

        const uint32_t sb = smb + AST_BASE + (uint32_t)(c & 1) * AST_SIZE;

        float acc[8][4];
        {
            const char* pB = sm + AST_BASE + (size_t)(c & 1) * AST_SIZE + AST_P
                           + (wid * 16 + er) * 288 + ec * 4;
#pragma unroll
            for (int nt = 0; nt < 8; nt++) {
                float2 p0 = *(const float2*)(pB + nt * 32);
                float2 p1 = *(const float2*)(pB + nt * 32 + 8 * 288);
                acc[nt][0] = 8.f * p0.x; acc[nt][1] = 8.f * p0.y;
                acc[nt][2] = 8.f * p1.x; acc[nt][3] = 8.f * p1.y;
            }
        }

        {
            const uint32_t qbh = smb + AQ_H, qbl = smb + AQ_L;
            const uint32_t kbh = sb + AST_KH, kbl = sb + AST_KL;
#pragma unroll
            for (int ks = 0; ks < 4; ks++) {
                uint32_t qf_h[4], qf_l[4], kh[4][4], kl[4][4];
                ldsm4(qf_h, qbh + swz(wid * 16 + arl, ks * 2 + acs));
                ldsm4(qf_l, qbl + swz(wid * 16 + arl, ks * 2 + acs));
#pragma unroll
                for (int p = 0; p < 4; p++) {
                    ldsm4(kh[p], kbh + swz(p * 16 + brl, ks * 2 + bcs));
                    ldsm4(kl[p], kbl + swz(p * 16 + brl, ks * 2 + bcs));
                }
#pragma unroll
                for (int nt = 0; nt < 8; nt++)
                    mma16816(acc[nt], qf_h, &kh[nt >> 1][(nt & 1) * 2]);
#pragma unroll
                for (int nt = 0; nt < 8; nt++)
                    mma16816(acc[nt], qf_h, &kl[nt >> 1][(nt & 1) * 2]);
#pragma unroll
                for (int nt = 0; nt < 8; nt++)
                    mma16816(acc[nt], qf_l, &kh[nt >> 1][(nt & 1) * 2]);
            }
        }

        float tmax0 = mv0, tmax1 = mv1;
#pragma unroll
        for (int nt = 0; nt < 8; nt++) {
            acc[nt][0] *= SCALE; acc[nt][1] *= SCALE;
            acc[nt][2] *= SCALE; acc[nt][3] *= SCALE;
            tmax0 = fmaxf(tmax0, fmaxf(acc[nt][0], acc[nt][1]));
            tmax1 = fmaxf(tmax1, fmaxf(acc[nt][2], acc[nt][3]));
        }
        tmax0 = fmaxf(tmax0, __shfl_xor_sync(0xffffffffu, tmax0, 1));
        tmax0 = fmaxf(tmax0, __shfl_xor_sync(0xffffffffu, tmax0, 2));
        tmax1 = fmaxf(tmax1, __shfl_xor_sync(0xffffffffu, tmax1, 1));
        tmax1 = fmaxf(tmax1, __shfl_xor_sync(0xffffffffu, tmax1, 2));

        float alpha0 = __expf(mv0 - tmax0);
        float alpha1 = __expf(mv1 - tmax1);
        mv0 = tmax0; mv1 = tmax1;

        uint32_t pa_h[4][4], pa_l[4][4];
        float la0 = 0.f, la1 = 0.f;
#pragma unroll
        for (int nt = 0; nt < 8; nt++) {
            float p0 = __expf(acc[nt][0] - mv0);
            float p1 = __expf(acc[nt][1] - mv0);
            float p2 = __expf(acc[nt][2] - mv1);
            float p3 = __expf(acc[nt][3] - mv1);
            la0 += p0 + p1; la1 += p2 + p3;
            __nv_bfloat162 h01 = __floats2bfloat162_rn(p0, p1);
            __nv_bfloat162 h23 = __floats2bfloat162_rn(p2, p3);
            float q0f = p0 - __low2float(h01), q1f = p1 - __high2float(h01);
            float q2f = p2 - __low2float(h23), q3f = p3 - __high2float(h23);
            int t = nt >> 1, base = (nt & 1) * 2;
            pa_h[t][base + 0] = *(uint32_t*)&h01;
            pa_h[t][base + 1] = *(uint32_t*)&h23;
            pa_l[t][base + 0] = packbf(q0f, q1f);
            pa_l[t][base + 1] = packbf(q2f, q3f);
        }
        l0 = l0 * alpha0 + la0;
        l1 = l1 * alpha1 + la1;

#pragma unroll
        for (int nt = 0; nt < 8; nt++) {
            O[nt][0] *= alpha0; O[nt][1] *= alpha0;
            O[nt][2] *= alpha1; O[nt][3] *= alpha1;
        }

        {
            const uint32_t vbh = sb + AST_VH, vbl = sb + AST_VL;
#pragma unroll
            for (int ks = 0; ks < 4; ks++) {
                uint32_t vh[4][4], vl[4][4];
#pragma unroll
                for (int tp = 0; tp < 4; tp++) {
                    ldsm4t(vh[tp], vbh + swz(ks * 16 + arl, tp * 2 + acs));
                    ldsm4t(vl[tp], vbl + swz(ks * 16 + arl, tp * 2 + acs));
                }
#pragma unroll
                for (int nt = 0; nt < 8; nt++)
                    mma16816(O[nt], pa_h[ks], &vh[nt >> 1][(nt & 1) * 2]);
#pragma unroll
                for (int nt = 0; nt < 8; nt++)
                    mma16816(O[nt], pa_h[ks], &vl[nt >> 1][(nt & 1) * 2]);
#pragma unroll
                for (int nt = 0; nt < 8; nt++)
                    mma16816(O[nt], pa_l[ks], &vh[nt >> 1][(nt & 1) * 2]);
            }
        }
    }

    l0 += __shfl_xor_sync(0xffffffffu, l0, 1);
    l0 += __shfl_xor_sync(0xffffffffu, l0, 2);
    l1 += __shfl_xor_sync(0xffffffffu, l1, 1);
    l1 += __shfl_xor_sync(0xffffffffu, l1, 2);
    float inv0 = 1.f / l0, inv1 = 1.f / l1;

    const size_t row0 = (size_t)(b * LQ + q0 + wid * 16 + er);
#pragma unroll
    for (int nt = 0; nt < 8; nt++) {
        int col = h * HDIM + nt * 8 + ec;
        float v0 = O[nt][0] * inv0, v1 = O[nt][1] * inv0;
        float v2 = O[nt][2] * inv1, v3 = O[nt][3] * inv1;
        __nv_bfloat162 h01 = __floats2bfloat162_rn(v0, v1);
        __nv_bfloat162 h23 = __floats2bfloat162_rn(v2, v3);
        float q0f = v0 - __low2float(h01), q1f = v1 - __high2float(h01);
        float q2f = v2 - __low2float(h23), q3f = v3 - __high2float(h23);
        size_t offA = row0 * DIMC + col;
        size_t offB = (row0 + 8) * DIMC + col;
        *(uint32_t*)(Oh + offA) = *(uint32_t*)&h01;
        *(uint32_t*)(Ol + offA) = packbf(q0f, q1f);
        *(uint32_t*)(Oh + offB) = *(uint32_t*)&h23;
        *(uint32_t*)(Ol + offB) = packbf(q2f, q3f);
    }
}

// ---------------------------------------------------------------------------
extern "C" void kernel_launch(void* const* d_in, const int* in_sizes, int n_in,
                              void* d_out, int out_size)
{
    (void)in_sizes; (void)n_in; (void)out_size;
    const float* q     = (const float*)d_in[0];
    const float* kv    = (const float*)d_in[1];
    const float* pos   = (const float*)d_in[2];
    const float* Wq    = (const float*)d_in[3];
    const float* Wkv   = (const float*)d_in[4];
    const float* Wproj = (const float*)d_in[5];
    const float* bproj = (const float*)d_in[6];
    float* out = (float*)d_out;

    __nv_bfloat16 *qh, *ql, *kvh, *kvl, *wqh, *wql, *wkh, *wkl, *wph, *wpl;
    __nv_bfloat16 *PQh, *PQl, *PKh, *PKl, *oh, *ol;
    cudaGetSymbolAddress((void**)&qh,  g_qh);   cudaGetSymbolAddress((void**)&ql,  g_ql);
    cudaGetSymbolAddress((void**)&kvh, g_kvh);  cudaGetSymbolAddress((void**)&kvl, g_kvl);
    cudaGetSymbolAddress((void**)&wqh, g_wqh);  cudaGetSymbolAddress((void**)&wql, g_wql);
    cudaGetSymbolAddress((void**)&wkh, g_wkh);  cudaGetSymbolAddress((void**)&wkl, g_wkl);
    cudaGetSymbolAddress((void**)&wph, g_wph);  cudaGetSymbolAddress((void**)&wpl, g_wpl);
    cudaGetSymbolAddress((void**)&PQh, g_PQh);  cudaGetSymbolAddress((void**)&PQl, g_PQl);
    cudaGetSymbolAddress((void**)&PKh, g_PKh);  cudaGetSymbolAddress((void**)&PKl, g_PKl);
    cudaGetSymbolAddress((void**)&oh,  g_oh);   cudaGetSymbolAddress((void**)&ol,  g_ol);

    static bool attr_done = false;
    if (!attr_done) {
        cudaFuncSetAttribute(gemm_qkv,  cudaFuncAttributeMaxDynamicSharedMemorySize, GEMM_SMEM);
        cudaFuncSetAttribute(gemm_proj, cudaFuncAttributeMaxDynamicSharedMemorySize, GEMM_SMEM);
        cudaFuncSetAttribute(attn_mma,  cudaFuncAttributeMaxDynamicSharedMemorySize, ATTN_SMEM);
        attr_done = true;
    }

    // one merged split kernel for all fp32 inputs
    {
        int grid = (int)((N4_TOT + 255) / 256);
        cvt_all<<<grid, 256>>>(
            (const float4*)q,   (uint2*)qh,  (uint2*)ql,
            (const float4*)kv,  (uint2*)kvh, (uint2*)kvl,
            (const float4*)Wq,  (uint2*)wqh, (uint2*)wql,
            (const float4*)Wkv, (uint2*)wkh, (uint2*)wkl,
            (const float4*)Wproj, (uint2*)wph, (uint2*)wpl);
    }

    // combined Q + KV projections -> split bf16
    gemm_qkv<<<2304, 256, GEMM_SMEM>>>(qh, ql, wqh, wql, PQh, PQl,
                                       kvh, kvl, wkh, wkl, PKh, PKl);

    // tensor-core flash attention -> split bf16 O
    attn_mma<<<dim3(LQ / 128, NHEADS, BATCH), 256, ATTN_SMEM>>>(
        PQh, PQl, PKh, PKl, pos, oh, ol);

    // output projection (fp32 + bias)
    gemm_proj<<<768, 256, GEMM_SMEM>>>(oh, ol, wph, wpl, bproj, out);
}